// round 5
// baseline (speedup 1.0000x reference)
#include <cuda_runtime.h>

#define BDIM 2048
#define TDIM 128
#define FDIM 64
#define HDIM 256
#define G3   768
#define OUTL 32
#define FCH  256

#define ROWS 16
#define RP   8
#define NTHR 256
#define NCTA (BDIM / ROWS)   // 128
#define PAD  18

typedef unsigned long long u64;

// ---------------- scratch (__device__ globals; no allocations) ----------------
__device__ float g_hs[(size_t)BDIM * TDIM * HDIM];   // 256 MB, layout [b][t][h]
__device__ float g_A[BDIM * TDIM];
__device__ float g_C[BDIM * TDIM];
__device__ float g_WtEncHh[HDIM * G3];   // [k][j]
__device__ float g_WtEncIh[FDIM * G3];   // [f][j]
__device__ float g_WtDecHh[HDIM * G3];   // [k][j]
__device__ float g_WtFc1[HDIM * FCH];    // [k][j]

// ---------------- helpers ----------------
__device__ __forceinline__ u64 pk2(float v) {
    u64 r; unsigned int u = __float_as_uint(v);
    asm("mov.b64 %0, {%1, %2};" : "=l"(r) : "r"(u), "r"(u));
    return r;
}
__device__ __forceinline__ u64 pk2p(float a, float b) {
    u64 r;
    asm("mov.b64 %0, {%1, %2};" : "=l"(r)
        : "r"(__float_as_uint(a)), "r"(__float_as_uint(b)));
    return r;
}
__device__ __forceinline__ float2 upk(u64 v) {
    unsigned int lo, hi;
    asm("mov.b64 {%0, %1}, %2;" : "=r"(lo), "=r"(hi) : "l"(v));
    return make_float2(__uint_as_float(lo), __uint_as_float(hi));
}
// packed fp32x2 FMA (sm_100+): acc = a*b + acc
__device__ __forceinline__ void fma2(u64& acc, u64 a, u64 b) {
    asm("fma.rn.f32x2 %0, %1, %2, %0;" : "+l"(acc) : "l"(a), "l"(b));
}
__device__ __forceinline__ u64 lds2(const float* p) {
    return *reinterpret_cast<const u64*>(p);
}
__device__ __forceinline__ float sigmoidf_(float x) {
    return 1.0f / (1.0f + __expf(-x));
}
__device__ __forceinline__ float tanhf_(float x) {
    float xx = fminf(fmaxf(x, -15.f), 15.f);
    float e = __expf(2.f * xx);
    return (e - 1.f) / (e + 1.f);
}

// ---------------- prep: weight transposes ----------------
__global__ void prep_kernel(const float* __restrict__ encWih,
                            const float* __restrict__ encWhh,
                            const float* __restrict__ decWhh,
                            const float* __restrict__ fc1W) {
    int i = blockIdx.x * blockDim.x + threadIdx.x;
    if (i < G3 * HDIM) {
        int j = i / HDIM, k = i % HDIM;
        g_WtEncHh[k * G3 + j] = encWhh[i];
        g_WtDecHh[k * G3 + j] = decWhh[i];
    }
    if (i < G3 * FDIM) {
        int j = i / FDIM, f = i % FDIM;
        g_WtEncIh[f * G3 + j] = encWih[i];
    }
    if (i < FCH * HDIM) {
        int j = i / HDIM, k = i % HDIM;
        g_WtFc1[k * FCH + j] = fc1W[i];
    }
}

// ---------------- encoder: persistent over all 128 steps ----------------
__global__ void __launch_bounds__(NTHR)
encoder_kernel(const float* __restrict__ x, const float* __restrict__ h0,
               const float* __restrict__ bih, const float* __restrict__ bhh) {
    __shared__ float sh_h[HDIM * PAD];   // [k][row]
    __shared__ float sh_x[FDIM * PAD];   // [f][row]
    const int t = threadIdx.x;           // hidden unit j
    const int row0 = blockIdx.x * ROWS;

    const float bias_r  = bih[t]          + bhh[t];
    const float bias_z  = bih[t + HDIM]   + bhh[t + HDIM];
    const float bias_in = bih[t + 2*HDIM];
    const float bias_hn = bhh[t + 2*HDIM];

    for (int i = t; i < ROWS * HDIM; i += NTHR) {
        int r = i / HDIM, k = i % HDIM;
        sh_h[k * PAD + r] = h0[(size_t)(row0 + r) * HDIM + k];
    }
    __syncthreads();

    const float* __restrict__ Whh = g_WtEncHh;
    const float* __restrict__ Wih = g_WtEncIh;

    for (int step = 0; step < TDIM; ++step) {
        // stage x_t tile
        for (int i = t; i < ROWS * FDIM; i += NTHR) {
            int r = i / FDIM, f = i % FDIM;
            sh_x[f * PAD + r] = x[((size_t)(row0 + r) * TDIM + step) * FDIM + f];
        }
        __syncthreads();

        u64 ar[RP], az[RP], ain[RP], ahn[RP];
        u64 br2 = pk2(bias_r), bz2 = pk2(bias_z), bi2 = pk2(bias_in), bh2 = pk2(bias_hn);
        #pragma unroll
        for (int rp = 0; rp < RP; ++rp) { ar[rp]=br2; az[rp]=bz2; ain[rp]=bi2; ahn[rp]=bh2; }

        // input projection  gi = x @ Wih^T
        #pragma unroll 4
        for (int f = 0; f < FDIM; ++f) {
            u64 wr = pk2(Wih[f * G3 + t]);
            u64 wz = pk2(Wih[f * G3 + t + HDIM]);
            u64 wn = pk2(Wih[f * G3 + t + 2*HDIM]);
            #pragma unroll
            for (int rp = 0; rp < RP; ++rp) {
                u64 xv = lds2(&sh_x[f * PAD + 2*rp]);
                fma2(ar[rp],  xv, wr);
                fma2(az[rp],  xv, wz);
                fma2(ain[rp], xv, wn);
            }
        }
        // hidden projection gh = h @ Whh^T
        #pragma unroll 4
        for (int k = 0; k < HDIM; ++k) {
            u64 wr = pk2(Whh[k * G3 + t]);
            u64 wz = pk2(Whh[k * G3 + t + HDIM]);
            u64 wn = pk2(Whh[k * G3 + t + 2*HDIM]);
            #pragma unroll
            for (int rp = 0; rp < RP; ++rp) {
                u64 hv = lds2(&sh_h[k * PAD + 2*rp]);
                fma2(ar[rp],  hv, wr);
                fma2(az[rp],  hv, wz);
                fma2(ahn[rp], hv, wn);
            }
        }

        float hnew[ROWS];
        #pragma unroll
        for (int rp = 0; rp < RP; ++rp) {
            float2 vr = upk(ar[rp]),  vz = upk(az[rp]);
            float2 vi = upk(ain[rp]), vh = upk(ahn[rp]);
            float r0 = sigmoidf_(vr.x), r1 = sigmoidf_(vr.y);
            float z0 = sigmoidf_(vz.x), z1 = sigmoidf_(vz.y);
            float n0 = tanhf_(vi.x + r0 * vh.x);
            float n1 = tanhf_(vi.y + r1 * vh.y);
            float o0 = sh_h[t * PAD + 2*rp];
            float o1 = sh_h[t * PAD + 2*rp + 1];
            hnew[2*rp]     = (1.f - z0) * n0 + z0 * o0;
            hnew[2*rp + 1] = (1.f - z1) * n1 + z1 * o1;
        }
        __syncthreads();
        size_t base = ((size_t)row0 * TDIM + step) * HDIM + t;
        #pragma unroll
        for (int r = 0; r < ROWS; ++r) {
            sh_h[t * PAD + r] = hnew[r];
            g_hs[base + (size_t)r * TDIM * HDIM] = hnew[r];
        }
        __syncthreads();
    }
}

// ---------------- A/C precompute: A=hs·Wq, C=hs·bq ----------------
__global__ void ac_kernel(const float* __restrict__ Wq, const float* __restrict__ bq) {
    int warp = (blockIdx.x * blockDim.x + threadIdx.x) >> 5;
    int lane = threadIdx.x & 31;
    if (warp >= BDIM * TDIM) return;
    const float* hp = g_hs + (size_t)warp * HDIM;
    float a = 0.f, c = 0.f;
    #pragma unroll
    for (int k = lane; k < HDIM; k += 32) {
        float hv = hp[k];
        a = fmaf(hv, Wq[k], a);
        c = fmaf(hv, bq[k], c);
    }
    #pragma unroll
    for (int off = 16; off; off >>= 1) {
        a += __shfl_xor_sync(0xffffffffu, a, off);
        c += __shfl_xor_sync(0xffffffffu, c, off);
    }
    if (lane == 0) { g_A[warp] = a; g_C[warp] = c; }
}

// ---------------- decoder: persistent over all 32 steps ----------------
__global__ void __launch_bounds__(NTHR)
decoder_kernel(const float* __restrict__ x,
               const float* __restrict__ dWih, const float* __restrict__ dbih,
               const float* __restrict__ dbhh,
               const float* __restrict__ fc1b, const float* __restrict__ fc2W,
               const float* __restrict__ fc2b, float* __restrict__ out) {
    __shared__ float sh_ctx[HDIM * PAD];      // packed ctx, later reused for hd
    __shared__ float sh_A[ROWS][TDIM];
    __shared__ float sh_C[ROWS][TDIM];
    __shared__ float sh_w[ROWS][TDIM];
    __shared__ float sh_prev[ROWS];
    __shared__ float sh_red[8][ROWS];

    const int t = threadIdx.x;
    const int row0 = blockIdx.x * ROWS;
    const int wp = t >> 5, lane = t & 31;

    for (int i = t; i < ROWS * TDIM; i += NTHR) {
        int r = i / TDIM, tt = i % TDIM;
        sh_A[r][tt] = g_A[(row0 + r) * TDIM + tt];
        sh_C[r][tt] = g_C[(row0 + r) * TDIM + tt];
    }
    if (t < ROWS)
        sh_prev[t] = x[((size_t)(row0 + t) * TDIM + (TDIM - 1)) * FDIM + 0];

    const float dbr  = dbih[t]          + dbhh[t];
    const float dbz  = dbih[t + HDIM]   + dbhh[t + HDIM];
    const float dbin = dbih[t + 2*HDIM];
    const float dbhn = dbhh[t + 2*HDIM];
    const float wir  = dWih[t], wiz = dWih[t + HDIM], win = dWih[t + 2*HDIM];
    const float f1b  = fc1b[t];
    const float f2w  = fc2W[t];
    const float f2b  = fc2b[0];
    const float scale = 0.0625f;   // 1/sqrt(256)
    __syncthreads();

    for (int step = 0; step < OUTL; ++step) {
        // ---- scores + softmax (warp handles 2 rows) ----
        #pragma unroll
        for (int rr = 0; rr < 2; ++rr) {
            int r = wp * 2 + rr;
            float pv = sh_prev[r];
            float sv[4], m = -1e30f;
            #pragma unroll
            for (int i = 0; i < 4; ++i) {
                int tt = lane + 32 * i;
                float s = (pv * sh_A[r][tt] + sh_C[r][tt]) * scale;
                sv[i] = s; m = fmaxf(m, s);
            }
            #pragma unroll
            for (int off = 16; off; off >>= 1) m = fmaxf(m, __shfl_xor_sync(0xffffffffu, m, off));
            float sum = 0.f;
            #pragma unroll
            for (int i = 0; i < 4; ++i) { sv[i] = __expf(sv[i] - m); sum += sv[i]; }
            #pragma unroll
            for (int off = 16; off; off >>= 1) sum += __shfl_xor_sync(0xffffffffu, sum, off);
            float inv = 1.f / sum;
            #pragma unroll
            for (int i = 0; i < 4; ++i) sh_w[r][lane + 32 * i] = sv[i] * inv;
        }
        __syncthreads();

        // ---- ctx[row][t] = sum_tt w * hs  (thread = h index) ----
        float ctx[ROWS];
        #pragma unroll
        for (int r = 0; r < ROWS; ++r) {
            const float* hp = g_hs + (size_t)(row0 + r) * TDIM * HDIM + t;
            float acc = 0.f;
            #pragma unroll 8
            for (int tt = 0; tt < TDIM; ++tt)
                acc = fmaf(sh_w[r][tt], hp[(size_t)tt * HDIM], acc);
            ctx[r] = acc;
        }
        __syncthreads();
        #pragma unroll
        for (int r = 0; r < ROWS; ++r) sh_ctx[t * PAD + r] = ctx[r];
        __syncthreads();

        // ---- GRU cell: x=prev (scalar), h=ctx ----
        u64 ar[RP], az[RP], ain[RP], ahn[RP];
        #pragma unroll
        for (int rp = 0; rp < RP; ++rp) {
            float p0 = sh_prev[2*rp], p1 = sh_prev[2*rp + 1];
            ar[rp]  = pk2p(fmaf(p0, wir, dbr),  fmaf(p1, wir, dbr));
            az[rp]  = pk2p(fmaf(p0, wiz, dbz),  fmaf(p1, wiz, dbz));
            ain[rp] = pk2p(fmaf(p0, win, dbin), fmaf(p1, win, dbin));
            ahn[rp] = pk2(dbhn);
        }
        #pragma unroll 4
        for (int k = 0; k < HDIM; ++k) {
            u64 wr = pk2(g_WtDecHh[k * G3 + t]);
            u64 wz = pk2(g_WtDecHh[k * G3 + t + HDIM]);
            u64 wn = pk2(g_WtDecHh[k * G3 + t + 2*HDIM]);
            #pragma unroll
            for (int rp = 0; rp < RP; ++rp) {
                u64 cv = lds2(&sh_ctx[k * PAD + 2*rp]);
                fma2(ar[rp],  cv, wr);
                fma2(az[rp],  cv, wz);
                fma2(ahn[rp], cv, wn);
            }
        }
        float hd[ROWS];
        #pragma unroll
        for (int rp = 0; rp < RP; ++rp) {
            float2 vr = upk(ar[rp]),  vz = upk(az[rp]);
            float2 vi = upk(ain[rp]), vh = upk(ahn[rp]);
            float r0 = sigmoidf_(vr.x), r1 = sigmoidf_(vr.y);
            float z0 = sigmoidf_(vz.x), z1 = sigmoidf_(vz.y);
            float n0 = tanhf_(vi.x + r0 * vh.x);
            float n1 = tanhf_(vi.y + r1 * vh.y);
            hd[2*rp]     = (1.f - z0) * n0 + z0 * ctx[2*rp];
            hd[2*rp + 1] = (1.f - z1) * n1 + z1 * ctx[2*rp + 1];
        }
        __syncthreads();                       // done reading sh_ctx (ctx)
        #pragma unroll
        for (int r = 0; r < ROWS; ++r) sh_ctx[t * PAD + r] = hd[r];
        __syncthreads();

        // ---- fc1 (relu) ----
        u64 a1[RP]; u64 b1 = pk2(f1b);
        #pragma unroll
        for (int rp = 0; rp < RP; ++rp) a1[rp] = b1;
        #pragma unroll 4
        for (int k = 0; k < HDIM; ++k) {
            u64 wf = pk2(g_WtFc1[k * FCH + t]);
            #pragma unroll
            for (int rp = 0; rp < RP; ++rp) {
                u64 hv = lds2(&sh_ctx[k * PAD + 2*rp]);
                fma2(a1[rp], hv, wf);
            }
        }
        // ---- fc2: cross-thread reduce ----
        float p[ROWS];
        #pragma unroll
        for (int rp = 0; rp < RP; ++rp) {
            float2 v = upk(a1[rp]);
            p[2*rp]     = fmaxf(v.x, 0.f) * f2w;
            p[2*rp + 1] = fmaxf(v.y, 0.f) * f2w;
        }
        #pragma unroll
        for (int off = 16; off; off >>= 1) {
            #pragma unroll
            for (int r = 0; r < ROWS; ++r)
                p[r] += __shfl_xor_sync(0xffffffffu, p[r], off);
        }
        if (lane == 0) {
            #pragma unroll
            for (int r = 0; r < ROWS; ++r) sh_red[wp][r] = p[r];
        }
        __syncthreads();
        if (t < ROWS) {
            float s = f2b;
            #pragma unroll
            for (int w = 0; w < 8; ++w) s += sh_red[w][t];
            out[(size_t)(row0 + t) * OUTL + step] = s;
            sh_prev[t] = s;
        }
        __syncthreads();
    }
}

// ---------------- launch ----------------
extern "C" void kernel_launch(void* const* d_in, const int* in_sizes, int n_in,
                              void* d_out, int out_size) {
    (void)in_sizes; (void)n_in; (void)out_size;
    const float* x       = (const float*)d_in[0];
    const float* h0      = (const float*)d_in[1];
    const float* enc_Wih = (const float*)d_in[2];
    const float* enc_Whh = (const float*)d_in[3];
    const float* enc_bih = (const float*)d_in[4];
    const float* enc_bhh = (const float*)d_in[5];
    const float* dec_Wih = (const float*)d_in[6];
    const float* dec_Whh = (const float*)d_in[7];
    const float* dec_bih = (const float*)d_in[8];
    const float* dec_bhh = (const float*)d_in[9];
    const float* attn_Wq = (const float*)d_in[10];
    const float* attn_bq = (const float*)d_in[11];
    const float* fc1_W   = (const float*)d_in[12];
    const float* fc1_b   = (const float*)d_in[13];
    const float* fc2_W   = (const float*)d_in[14];
    const float* fc2_b   = (const float*)d_in[15];
    float* out = (float*)d_out;

    prep_kernel<<<(G3 * HDIM + NTHR - 1) / NTHR, NTHR>>>(enc_Wih, enc_Whh, dec_Whh, fc1_W);
    encoder_kernel<<<NCTA, NTHR>>>(x, h0, enc_bih, enc_bhh);
    ac_kernel<<<(BDIM * TDIM) / 8, NTHR>>>(attn_Wq, attn_bq);
    decoder_kernel<<<NCTA, NTHR>>>(x, dec_Wih, dec_bih, dec_bhh,
                                   fc1_b, fc2_W, fc2_b, out);
}

// round 7
// speedup vs baseline: 1.3750x; 1.3750x over previous
#include <cuda_runtime.h>

#define BDIM 2048
#define TDIM 128
#define FDIM 64
#define HDIM 256
#define G3   768
#define OUTL 32
#define FCH  256

#define ROWS 16
#define RP   8
#define NTHR 256
#define NCTA (BDIM / ROWS)   // 128
#define PAD  18

typedef unsigned long long u64;

// ---------------- scratch (__device__ globals; no allocations) ----------------
__device__ float  g_hs[(size_t)BDIM * TDIM * HDIM];   // 256 MB, layout [b][t][h]
__device__ float  g_A[BDIM * TDIM];
__device__ float  g_C[BDIM * TDIM];
__device__ float2 g_Wrz[320 * 256];    // encoder cat [idx][j]: idx<64 = x-feat, else h-unit
__device__ float  g_Wn [320 * 256];
__device__ float2 g_DWrz[256 * 256];   // decoder Whh [k][j]
__device__ float  g_DWn [256 * 256];
__device__ float  g_WtFc1[HDIM * FCH]; // [k][j]

// ---------------- helpers ----------------
__device__ __forceinline__ u64 pk2(float v) {
    u64 r; unsigned int u = __float_as_uint(v);
    asm("mov.b64 %0, {%1, %2};" : "=l"(r) : "r"(u), "r"(u));
    return r;
}
__device__ __forceinline__ u64 pk2p(float a, float b) {
    u64 r;
    asm("mov.b64 %0, {%1, %2};" : "=l"(r)
        : "r"(__float_as_uint(a)), "r"(__float_as_uint(b)));
    return r;
}
__device__ __forceinline__ float2 upk(u64 v) {
    unsigned int lo, hi;
    asm("mov.b64 {%0, %1}, %2;" : "=r"(lo), "=r"(hi) : "l"(v));
    return make_float2(__uint_as_float(lo), __uint_as_float(hi));
}
__device__ __forceinline__ void fma2(u64& acc, u64 a, u64 b) {
    asm("fma.rn.f32x2 %0, %1, %2, %0;" : "+l"(acc) : "l"(a), "l"(b));
}
__device__ __forceinline__ u64 lds2(const float* p) {
    return *reinterpret_cast<const u64*>(p);
}
__device__ __forceinline__ float sigmoidf_(float x) {
    float e = __expf(-x);
    return __fdividef(1.0f, 1.0f + e);
}
__device__ __forceinline__ float tanhf_(float x) {
    float xx = fminf(fmaxf(x, -15.f), 15.f);
    float e = __expf(2.f * xx);
    return __fdividef(e - 1.f, e + 1.f);
}

// ---------------- prep: weight repack ----------------
__global__ void prep_kernel(const float* __restrict__ encWih,
                            const float* __restrict__ encWhh,
                            const float* __restrict__ decWhh,
                            const float* __restrict__ fc1W) {
    int i = blockIdx.x * blockDim.x + threadIdx.x;
    if (i < 320 * 256) {
        int row = i >> 8, j = i & 255;
        float wr, wz, wn;
        if (row < 64) {
            int f = row;
            wr = encWih[j * FDIM + f];
            wz = encWih[(j + HDIM) * FDIM + f];
            wn = encWih[(j + 2 * HDIM) * FDIM + f];
        } else {
            int k = row - 64;
            wr = encWhh[j * HDIM + k];
            wz = encWhh[(j + HDIM) * HDIM + k];
            wn = encWhh[(j + 2 * HDIM) * HDIM + k];
        }
        g_Wrz[i] = make_float2(wr, wz);
        g_Wn[i]  = wn;
    }
    if (i < 256 * 256) {
        int k = i >> 8, j = i & 255;
        g_DWrz[i] = make_float2(decWhh[j * HDIM + k], decWhh[(j + HDIM) * HDIM + k]);
        g_DWn[i]  = decWhh[(j + 2 * HDIM) * HDIM + k];
        g_WtFc1[k * FCH + j] = fc1W[j * HDIM + k];
    }
}

// ---------------- encoder: 512 threads, split-K across two 256-thread groups ----------------
#define ENC_SMEM_FLOATS (HDIM * PAD + 2 * FDIM * PAD + 256 * 49)
__global__ void __launch_bounds__(512, 1)
encoder_kernel(const float* __restrict__ x, const float* __restrict__ h0,
               const float* __restrict__ bih, const float* __restrict__ bhh) {
    extern __shared__ float sm[];
    float* sh_h    = sm;                          // [k][row] 256*PAD
    float* sh_x0   = sm + HDIM * PAD;             // [f][row] 64*PAD
    float* sh_x1   = sh_x0 + FDIM * PAD;
    float* sh_part = sh_x1 + FDIM * PAD;          // [256][49] g1 partials

    const int t  = threadIdx.x;
    const int g  = t >> 8;
    const int tj = t & 255;
    const int row0 = blockIdx.x * ROWS;

    const float bias_r  = bih[tj]            + bhh[tj];
    const float bias_z  = bih[tj + HDIM]     + bhh[tj + HDIM];
    const float bias_in = bih[tj + 2 * HDIM];
    const float bias_hn = bhh[tj + 2 * HDIM];

    for (int i = t; i < ROWS * HDIM; i += 512) {
        int r = i >> 8, k = i & 255;
        sh_h[k * PAD + r] = h0[(size_t)(row0 + r) * HDIM + k];
    }
    for (int i = t; i < ROWS * FDIM; i += 512) {
        int r = i >> 6, f = i & 63;
        sh_x0[f * PAD + r] = x[((size_t)(row0 + r) * TDIM + 0) * FDIM + f];
    }
    __syncthreads();

    const float2* __restrict__ Wrz = g_Wrz;
    const float*  __restrict__ Wn  = g_Wn;

    int buf = 0;
    for (int step = 0; step < TDIM; ++step) {
        float* xb = buf ? sh_x1 : sh_x0;
        float* xn = buf ? sh_x0 : sh_x1;

        u64 ar[RP], az[RP], an1[RP], an2[RP];
        if (g == 0) {
            u64 br2 = pk2(bias_r), bz2 = pk2(bias_z), bi2 = pk2(bias_in), bh2 = pk2(bias_hn);
            #pragma unroll
            for (int rp = 0; rp < RP; ++rp) { ar[rp]=br2; az[rp]=bz2; an1[rp]=bi2; an2[rp]=bh2; }
            // x projection (f = 0..63) : wn accumulates into i_n (an1)
            #pragma unroll 2
            for (int f = 0; f < FDIM; ++f) {
                float2 w  = Wrz[f * 256 + tj];
                float  wn = Wn [f * 256 + tj];
                u64 wr2 = pk2(w.x), wz2 = pk2(w.y), wn2 = pk2(wn);
                #pragma unroll
                for (int rp = 0; rp < RP; ++rp) {
                    u64 v = lds2(&xb[f * PAD + 2 * rp]);
                    fma2(ar[rp],  v, wr2);
                    fma2(az[rp],  v, wz2);
                    fma2(an1[rp], v, wn2);
                }
            }
            // h projection k = 0..95 : wn accumulates into h_n (an2)
            #pragma unroll 2
            for (int k = 0; k < 96; ++k) {
                float2 w  = Wrz[(64 + k) * 256 + tj];
                float  wn = Wn [(64 + k) * 256 + tj];
                u64 wr2 = pk2(w.x), wz2 = pk2(w.y), wn2 = pk2(wn);
                #pragma unroll
                for (int rp = 0; rp < RP; ++rp) {
                    u64 v = lds2(&sh_h[k * PAD + 2 * rp]);
                    fma2(ar[rp],  v, wr2);
                    fma2(az[rp],  v, wz2);
                    fma2(an2[rp], v, wn2);
                }
            }
        } else {
            u64 z0 = pk2(0.f);
            #pragma unroll
            for (int rp = 0; rp < RP; ++rp) { ar[rp]=z0; az[rp]=z0; an1[rp]=z0; an2[rp]=z0; }
            // h projection k = 96..255
            #pragma unroll 2
            for (int k = 96; k < 256; ++k) {
                float2 w  = Wrz[(64 + k) * 256 + tj];
                float  wn = Wn [(64 + k) * 256 + tj];
                u64 wr2 = pk2(w.x), wz2 = pk2(w.y), wn2 = pk2(wn);
                #pragma unroll
                for (int rp = 0; rp < RP; ++rp) {
                    u64 v = lds2(&sh_h[k * PAD + 2 * rp]);
                    fma2(ar[rp],  v, wr2);
                    fma2(az[rp],  v, wz2);
                    fma2(an2[rp], v, wn2);
                }
            }
            // publish partials
            float* pp = sh_part + tj * 49;
            #pragma unroll
            for (int rp = 0; rp < RP; ++rp) {
                float2 v = upk(ar[rp]);  pp[2*rp]      = v.x; pp[2*rp + 1]      = v.y;
                float2 w = upk(az[rp]);  pp[16 + 2*rp] = w.x; pp[16 + 2*rp + 1] = w.y;
                float2 h = upk(an2[rp]); pp[32 + 2*rp] = h.x; pp[32 + 2*rp + 1] = h.y;
            }
        }
        __syncthreads();

        if (g == 0) {
            const float* pp = sh_part + tj * 49;
            float hnew[ROWS];
            #pragma unroll
            for (int rp = 0; rp < RP; ++rp) {
                float2 vr = upk(ar[rp]);  vr.x += pp[2*rp];      vr.y += pp[2*rp + 1];
                float2 vz = upk(az[rp]);  vz.x += pp[16 + 2*rp]; vz.y += pp[16 + 2*rp + 1];
                float2 vi = upk(an1[rp]);
                float2 vh = upk(an2[rp]); vh.x += pp[32 + 2*rp]; vh.y += pp[32 + 2*rp + 1];
                float r0 = sigmoidf_(vr.x), r1 = sigmoidf_(vr.y);
                float z0 = sigmoidf_(vz.x), z1 = sigmoidf_(vz.y);
                float n0 = tanhf_(vi.x + r0 * vh.x);
                float n1 = tanhf_(vi.y + r1 * vh.y);
                float o0 = sh_h[tj * PAD + 2 * rp];
                float o1 = sh_h[tj * PAD + 2 * rp + 1];
                hnew[2*rp]     = (1.f - z0) * n0 + z0 * o0;
                hnew[2*rp + 1] = (1.f - z1) * n1 + z1 * o1;
            }
            size_t base = ((size_t)row0 * TDIM + step) * HDIM + tj;
            #pragma unroll
            for (int r = 0; r < ROWS; ++r) {
                sh_h[tj * PAD + r] = hnew[r];
                g_hs[base + (size_t)r * TDIM * HDIM] = hnew[r];
            }
        } else if (step + 1 < TDIM) {
            for (int i = tj; i < ROWS * FDIM; i += 256) {
                int r = i >> 6, f = i & 63;
                xn[f * PAD + r] = x[((size_t)(row0 + r) * TDIM + (step + 1)) * FDIM + f];
            }
        }
        buf ^= 1;
        __syncthreads();
    }
}

// ---------------- A/C precompute: A=hs·Wq, C=hs·bq ----------------
__global__ void ac_kernel(const float* __restrict__ Wq, const float* __restrict__ bq) {
    int warp = (blockIdx.x * blockDim.x + threadIdx.x) >> 5;
    int lane = threadIdx.x & 31;
    if (warp >= BDIM * TDIM) return;
    const float* hp = g_hs + (size_t)warp * HDIM;
    float a = 0.f, c = 0.f;
    #pragma unroll
    for (int k = lane; k < HDIM; k += 32) {
        float hv = hp[k];
        a = fmaf(hv, Wq[k], a);
        c = fmaf(hv, bq[k], c);
    }
    #pragma unroll
    for (int off = 16; off; off >>= 1) {
        a += __shfl_xor_sync(0xffffffffu, a, off);
        c += __shfl_xor_sync(0xffffffffu, c, off);
    }
    if (lane == 0) { g_A[warp] = a; g_C[warp] = c; }
}

// ---------------- decoder: persistent over all 32 steps ----------------
__global__ void __launch_bounds__(NTHR)
decoder_kernel(const float* __restrict__ x,
               const float* __restrict__ dWih, const float* __restrict__ dbih,
               const float* __restrict__ dbhh,
               const float* __restrict__ fc1b, const float* __restrict__ fc2W,
               const float* __restrict__ fc2b, float* __restrict__ out) {
    __shared__ float sh_ctx[HDIM * PAD];      // packed ctx, later reused for hd
    __shared__ float sh_A[ROWS][TDIM];
    __shared__ float sh_C[ROWS][TDIM];
    __shared__ float sh_w[ROWS][TDIM];
    __shared__ float sh_prev[ROWS];
    __shared__ float sh_red[8][ROWS];

    const int t = threadIdx.x;
    const int row0 = blockIdx.x * ROWS;
    const int wp = t >> 5, lane = t & 31;

    for (int i = t; i < ROWS * TDIM; i += NTHR) {
        int r = i / TDIM, tt = i % TDIM;
        sh_A[r][tt] = g_A[(row0 + r) * TDIM + tt];
        sh_C[r][tt] = g_C[(row0 + r) * TDIM + tt];
    }
    if (t < ROWS)
        sh_prev[t] = x[((size_t)(row0 + t) * TDIM + (TDIM - 1)) * FDIM + 0];

    const float dbr  = dbih[t]          + dbhh[t];
    const float dbz  = dbih[t + HDIM]   + dbhh[t + HDIM];
    const float dbin = dbih[t + 2*HDIM];
    const float dbhn = dbhh[t + 2*HDIM];
    const float wir  = dWih[t], wiz = dWih[t + HDIM], win = dWih[t + 2*HDIM];
    const float f1b  = fc1b[t];
    const float f2w  = fc2W[t];
    const float f2b  = fc2b[0];
    const float scale = 0.0625f;   // 1/sqrt(256)
    __syncthreads();

    for (int step = 0; step < OUTL; ++step) {
        // ---- scores + softmax (warp handles 2 rows) ----
        #pragma unroll
        for (int rr = 0; rr < 2; ++rr) {
            int r = wp * 2 + rr;
            float pv = sh_prev[r];
            float sv[4], m = -1e30f;
            #pragma unroll
            for (int i = 0; i < 4; ++i) {
                int tt = lane + 32 * i;
                float s = (pv * sh_A[r][tt] + sh_C[r][tt]) * scale;
                sv[i] = s; m = fmaxf(m, s);
            }
            #pragma unroll
            for (int off = 16; off; off >>= 1) m = fmaxf(m, __shfl_xor_sync(0xffffffffu, m, off));
            float sum = 0.f;
            #pragma unroll
            for (int i = 0; i < 4; ++i) { sv[i] = __expf(sv[i] - m); sum += sv[i]; }
            #pragma unroll
            for (int off = 16; off; off >>= 1) sum += __shfl_xor_sync(0xffffffffu, sum, off);
            float inv = __fdividef(1.f, sum);
            #pragma unroll
            for (int i = 0; i < 4; ++i) sh_w[r][lane + 32 * i] = sv[i] * inv;
        }
        __syncthreads();

        // ---- ctx[row] = sum_tt w * hs, tt-outer for MLP (16 indep LDG per tt) ----
        float ctx[ROWS];
        #pragma unroll
        for (int r = 0; r < ROWS; ++r) ctx[r] = 0.f;
        {
            const float* hp = g_hs + (size_t)row0 * TDIM * HDIM + t;
            #pragma unroll 2
            for (int tt = 0; tt < TDIM; ++tt) {
                const float* hq = hp + (size_t)tt * HDIM;
                #pragma unroll
                for (int r = 0; r < ROWS; ++r)
                    ctx[r] = fmaf(sh_w[r][tt], hq[(size_t)r * TDIM * HDIM], ctx[r]);
            }
        }
        __syncthreads();
        #pragma unroll
        for (int r = 0; r < ROWS; ++r) sh_ctx[t * PAD + r] = ctx[r];
        __syncthreads();

        // ---- GRU cell: x=prev (scalar), h=ctx ----
        u64 ar[RP], az[RP], ain[RP], ahn[RP];
        #pragma unroll
        for (int rp = 0; rp < RP; ++rp) {
            float p0 = sh_prev[2*rp], p1 = sh_prev[2*rp + 1];
            ar[rp]  = pk2p(fmaf(p0, wir, dbr),  fmaf(p1, wir, dbr));
            az[rp]  = pk2p(fmaf(p0, wiz, dbz),  fmaf(p1, wiz, dbz));
            ain[rp] = pk2p(fmaf(p0, win, dbin), fmaf(p1, win, dbin));
            ahn[rp] = pk2(dbhn);
        }
        #pragma unroll 2
        for (int k = 0; k < HDIM; ++k) {
            float2 w  = g_DWrz[k * 256 + t];
            float  wn = g_DWn [k * 256 + t];
            u64 wr = pk2(w.x), wz = pk2(w.y), wn2 = pk2(wn);
            #pragma unroll
            for (int rp = 0; rp < RP; ++rp) {
                u64 cv = lds2(&sh_ctx[k * PAD + 2*rp]);
                fma2(ar[rp],  cv, wr);
                fma2(az[rp],  cv, wz);
                fma2(ahn[rp], cv, wn2);
            }
        }
        float hd[ROWS];
        #pragma unroll
        for (int rp = 0; rp < RP; ++rp) {
            float2 vr = upk(ar[rp]),  vz = upk(az[rp]);
            float2 vi = upk(ain[rp]), vh = upk(ahn[rp]);
            float r0 = sigmoidf_(vr.x), r1 = sigmoidf_(vr.y);
            float z0 = sigmoidf_(vz.x), z1 = sigmoidf_(vz.y);
            float n0 = tanhf_(vi.x + r0 * vh.x);
            float n1 = tanhf_(vi.y + r1 * vh.y);
            hd[2*rp]     = (1.f - z0) * n0 + z0 * ctx[2*rp];
            hd[2*rp + 1] = (1.f - z1) * n1 + z1 * ctx[2*rp + 1];
        }
        __syncthreads();                       // done reading sh_ctx (ctx)
        #pragma unroll
        for (int r = 0; r < ROWS; ++r) sh_ctx[t * PAD + r] = hd[r];
        __syncthreads();

        // ---- fc1 (relu) ----
        u64 a1[RP]; u64 b1 = pk2(f1b);
        #pragma unroll
        for (int rp = 0; rp < RP; ++rp) a1[rp] = b1;
        #pragma unroll 4
        for (int k = 0; k < HDIM; ++k) {
            u64 wf = pk2(g_WtFc1[k * FCH + t]);
            #pragma unroll
            for (int rp = 0; rp < RP; ++rp) {
                u64 hv = lds2(&sh_ctx[k * PAD + 2*rp]);
                fma2(a1[rp], hv, wf);
            }
        }
        // ---- fc2: cross-thread reduce ----
        float p[ROWS];
        #pragma unroll
        for (int rp = 0; rp < RP; ++rp) {
            float2 v = upk(a1[rp]);
            p[2*rp]     = fmaxf(v.x, 0.f) * f2w;
            p[2*rp + 1] = fmaxf(v.y, 0.f) * f2w;
        }
        #pragma unroll
        for (int off = 16; off; off >>= 1) {
            #pragma unroll
            for (int r = 0; r < ROWS; ++r)
                p[r] += __shfl_xor_sync(0xffffffffu, p[r], off);
        }
        if (lane == 0) {
            #pragma unroll
            for (int r = 0; r < ROWS; ++r) sh_red[wp][r] = p[r];
        }
        __syncthreads();
        if (t < ROWS) {
            float s = f2b;
            #pragma unroll
            for (int w = 0; w < 8; ++w) s += sh_red[w][t];
            out[(size_t)(row0 + t) * OUTL + step] = s;
            sh_prev[t] = s;
        }
        __syncthreads();
    }
}

// ---------------- launch ----------------
extern "C" void kernel_launch(void* const* d_in, const int* in_sizes, int n_in,
                              void* d_out, int out_size) {
    (void)in_sizes; (void)n_in; (void)out_size;
    const float* x       = (const float*)d_in[0];
    const float* h0      = (const float*)d_in[1];
    const float* enc_Wih = (const float*)d_in[2];
    const float* enc_Whh = (const float*)d_in[3];
    const float* enc_bih = (const float*)d_in[4];
    const float* enc_bhh = (const float*)d_in[5];
    const float* dec_Wih = (const float*)d_in[6];
    const float* dec_Whh = (const float*)d_in[7];
    const float* dec_bih = (const float*)d_in[8];
    const float* dec_bhh = (const float*)d_in[9];
    const float* attn_Wq = (const float*)d_in[10];
    const float* attn_bq = (const float*)d_in[11];
    const float* fc1_W   = (const float*)d_in[12];
    const float* fc1_b   = (const float*)d_in[13];
    const float* fc2_W   = (const float*)d_in[14];
    const float* fc2_b   = (const float*)d_in[15];
    float* out = (float*)d_out;

    const int enc_smem = ENC_SMEM_FLOATS * (int)sizeof(float);   // ~76 KB
    cudaFuncSetAttribute(encoder_kernel,
                         cudaFuncAttributeMaxDynamicSharedMemorySize, enc_smem);

    prep_kernel<<<(320 * 256 + NTHR - 1) / NTHR, NTHR>>>(enc_Wih, enc_Whh, dec_Whh, fc1_W);
    encoder_kernel<<<NCTA, 512, enc_smem>>>(x, h0, enc_bih, enc_bhh);
    ac_kernel<<<(BDIM * TDIM) / 8, NTHR>>>(attn_Wq, attn_bq);
    decoder_kernel<<<NCTA, NTHR>>>(x, dec_Wih, dec_bih, dec_bhh,
                                   fc1_b, fc2_W, fc2_b, out);
}

// round 10
// speedup vs baseline: 1.4195x; 1.0323x over previous
#include <cuda_runtime.h>
#include <cuda_fp16.h>

#define BDIM 2048
#define TDIM 128
#define FDIM 64
#define HDIM 256
#define G3   768
#define OUTL 32
#define FCH  256

#define ROWS 16
#define RP   8
#define NTHR 256
#define NCTA (BDIM / ROWS)   // 128
#define PAD  18
#define CHUNK 8
#define NCHUNK 20            // 160 cat-rows per group / 8

typedef unsigned long long u64;

// ---------------- scratch (__device__ globals; no allocations) ----------------
__device__ __half g_hsh[(size_t)BDIM * TDIM * HDIM];  // 128 MB fp16 [b][t][h]
__device__ float  g_A[BDIM * TDIM];
__device__ float  g_C[BDIM * TDIM];
__device__ float2 g_Wrz[320 * 256];    // encoder cat [idx][j]: idx<64 = x-feat, else h-unit
__device__ float  g_Wn [320 * 256];
__device__ float2 g_DWrz[256 * 256];   // decoder Whh [k][j]
__device__ float  g_DWn [256 * 256];
__device__ float  g_WtFc1[HDIM * FCH]; // [k][j]

// ---------------- helpers ----------------
__device__ __forceinline__ u64 pk2(float v) {
    u64 r; unsigned int u = __float_as_uint(v);
    asm("mov.b64 %0, {%1, %2};" : "=l"(r) : "r"(u), "r"(u));
    return r;
}
__device__ __forceinline__ u64 pk2p(float a, float b) {
    u64 r;
    asm("mov.b64 %0, {%1, %2};" : "=l"(r)
        : "r"(__float_as_uint(a)), "r"(__float_as_uint(b)));
    return r;
}
__device__ __forceinline__ float2 upk(u64 v) {
    unsigned int lo, hi;
    asm("mov.b64 {%0, %1}, %2;" : "=r"(lo), "=r"(hi) : "l"(v));
    return make_float2(__uint_as_float(lo), __uint_as_float(hi));
}
__device__ __forceinline__ void fma2(u64& acc, u64 a, u64 b) {
    asm("fma.rn.f32x2 %0, %1, %2, %0;" : "+l"(acc) : "l"(a), "l"(b));
}
__device__ __forceinline__ u64 lds2(const float* p) {
    return *reinterpret_cast<const u64*>(p);
}
__device__ __forceinline__ float sigmoidf_(float x) {
    float e = __expf(-x);
    return __fdividef(1.0f, 1.0f + e);
}
__device__ __forceinline__ float tanhf_(float x) {
    float xx = fminf(fmaxf(x, -15.f), 15.f);
    float e = __expf(2.f * xx);
    return __fdividef(e - 1.f, e + 1.f);
}

// ---------------- prep: weight repack ----------------
__global__ void prep_kernel(const float* __restrict__ encWih,
                            const float* __restrict__ encWhh,
                            const float* __restrict__ decWhh,
                            const float* __restrict__ fc1W) {
    int i = blockIdx.x * blockDim.x + threadIdx.x;
    if (i < 320 * 256) {
        int row = i >> 8, j = i & 255;
        float wr, wz, wn;
        if (row < 64) {
            int f = row;
            wr = encWih[j * FDIM + f];
            wz = encWih[(j + HDIM) * FDIM + f];
            wn = encWih[(j + 2 * HDIM) * FDIM + f];
        } else {
            int k = row - 64;
            wr = encWhh[j * HDIM + k];
            wz = encWhh[(j + HDIM) * HDIM + k];
            wn = encWhh[(j + 2 * HDIM) * HDIM + k];
        }
        g_Wrz[i] = make_float2(wr, wz);
        g_Wn[i]  = wn;
    }
    if (i < 256 * 256) {
        int k = i >> 8, j = i & 255;
        g_DWrz[i] = make_float2(decWhh[j * HDIM + k], decWhh[(j + HDIM) * HDIM + k]);
        g_DWn[i]  = decWhh[(j + 2 * HDIM) * HDIM + k];
        g_WtFc1[k * FCH + j] = fc1W[j * HDIM + k];
    }
}

// ---------------- encoder: 512 threads, split-K, staged weights, fused A/C ----------------
// smem float offsets
#define E_H    0                     // 256*PAD = 4608
#define E_X0   4608                  // 64*PAD  = 1152
#define E_X1   5760
#define E_PART 6912                  // 256*49  = 12544
#define E_WRZ  19456                 // float2: 2buf*2grp*8*256 = 8192 f2 = 16384 f
#define E_WN   35840                 // 2*2*8*256 = 8192 f
#define E_AC   44032                 // 8 warps * 16 rows * 2 = 256 f
#define ENC_SMEM_FLOATS 44288        // 177152 bytes

__global__ void __launch_bounds__(512, 1)
encoder_kernel(const float* __restrict__ x, const float* __restrict__ h0,
               const float* __restrict__ bih, const float* __restrict__ bhh,
               const float* __restrict__ attnWq, const float* __restrict__ attnBq) {
    extern __shared__ float sm[];
    float*  sh_h    = sm + E_H;
    float*  sh_x0   = sm + E_X0;
    float*  sh_x1   = sm + E_X1;
    float*  sh_part = sm + E_PART;
    float2* sh_wrz  = reinterpret_cast<float2*>(sm + E_WRZ);
    float*  sh_wn   = sm + E_WN;
    float*  sh_ac   = sm + E_AC;

    const int t  = threadIdx.x;
    const int g  = t >> 8;
    const int tj = t & 255;
    const int wp = tj >> 5;
    const int row0 = blockIdx.x * ROWS;

    const float bias_r  = bih[tj]            + bhh[tj];
    const float bias_z  = bih[tj + HDIM]     + bhh[tj + HDIM];
    const float bias_in = bih[tj + 2 * HDIM];
    const float bias_hn = bhh[tj + 2 * HDIM];
    const float wqv = attnWq[tj];
    const float bqv = attnBq[tj];

    for (int i = t; i < ROWS * HDIM; i += 512) {
        int r = i >> 8, k = i & 255;
        sh_h[k * PAD + r] = h0[(size_t)(row0 + r) * HDIM + k];
    }
    for (int i = t; i < ROWS * FDIM; i += 512) {
        int r = i >> 6, f = i & 63;
        sh_x0[f * PAD + r] = x[((size_t)(row0 + r) * TDIM + 0) * FDIM + f];
    }

    // prologue: stage chunk 0 into buf 0 (both groups' slices)
    #pragma unroll
    for (int i = t; i < 2 * CHUNK * 256; i += 512) {
        int grp = i >> 11;
        int idx = i & 2047;
        int cat = grp * 160 + (idx >> 8);
        int j = idx & 255;
        sh_wrz[grp * (CHUNK * 256) + idx] = g_Wrz[cat * 256 + j];
        sh_wn [grp * (CHUNK * 256) + idx] = g_Wn [cat * 256 + j];
    }
    __syncthreads();

    int buf = 0;
    for (int step = 0; step < TDIM; ++step) {
        float* xb = (step & 1) ? sh_x1 : sh_x0;
        float* xn = (step & 1) ? sh_x0 : sh_x1;

        u64 ar[RP], az[RP], an1[RP], an2[RP];
        if (g == 0) {
            u64 br2 = pk2(bias_r), bz2 = pk2(bias_z), bi2 = pk2(bias_in), bh2 = pk2(bias_hn);
            #pragma unroll
            for (int rp = 0; rp < RP; ++rp) { ar[rp]=br2; az[rp]=bz2; an1[rp]=bi2; an2[rp]=bh2; }
        } else {
            u64 z0 = pk2(0.f);
            #pragma unroll
            for (int rp = 0; rp < RP; ++rp) { ar[rp]=z0; az[rp]=z0; an1[rp]=z0; an2[rp]=z0; }
        }

        for (int c = 0; c < NCHUNK; ++c) {
            // stage next chunk into the other buffer (wraps to chunk 0 for next step)
            int nxt = c + 1; if (nxt == NCHUNK) nxt = 0;
            {
                int bo = (buf ^ 1) * 2;
                #pragma unroll
                for (int i = t; i < 2 * CHUNK * 256; i += 512) {
                    int grp = i >> 11;
                    int idx = i & 2047;
                    int cat = grp * 160 + nxt * CHUNK + (idx >> 8);
                    int j = idx & 255;
                    sh_wrz[(bo + grp) * (CHUNK * 256) + idx] = g_Wrz[cat * 256 + j];
                    sh_wn [(bo + grp) * (CHUNK * 256) + idx] = g_Wn [cat * 256 + j];
                }
            }
            // compute chunk c from current buffer
            const float2* wz  = sh_wrz + (buf * 2 + g) * (CHUNK * 256);
            const float*  wnp = sh_wn  + (buf * 2 + g) * (CHUNK * 256);
            const float* base;
            bool toN1 = false;
            if (g == 0) {
                if (c < 8) { base = xb + (c * CHUNK) * PAD; toN1 = true; }
                else       { base = sh_h + (c * CHUNK - 64) * PAD; }
            } else {
                base = sh_h + (96 + c * CHUNK) * PAD;
            }
            if (toN1) {
                #pragma unroll 2
                for (int kk = 0; kk < CHUNK; ++kk) {
                    float2 w = wz[kk * 256 + tj]; float wv = wnp[kk * 256 + tj];
                    u64 wr2 = pk2(w.x), wz2 = pk2(w.y), wn2 = pk2(wv);
                    #pragma unroll
                    for (int rp = 0; rp < RP; ++rp) {
                        u64 v = lds2(base + kk * PAD + 2 * rp);
                        fma2(ar[rp],  v, wr2);
                        fma2(az[rp],  v, wz2);
                        fma2(an1[rp], v, wn2);
                    }
                }
            } else {
                #pragma unroll 2
                for (int kk = 0; kk < CHUNK; ++kk) {
                    float2 w = wz[kk * 256 + tj]; float wv = wnp[kk * 256 + tj];
                    u64 wr2 = pk2(w.x), wz2 = pk2(w.y), wn2 = pk2(wv);
                    #pragma unroll
                    for (int rp = 0; rp < RP; ++rp) {
                        u64 v = lds2(base + kk * PAD + 2 * rp);
                        fma2(ar[rp],  v, wr2);
                        fma2(az[rp],  v, wz2);
                        fma2(an2[rp], v, wn2);
                    }
                }
            }
            __syncthreads();
            buf ^= 1;
        }

        if (g == 1) {
            float* pp = sh_part + tj * 49;
            #pragma unroll
            for (int rp = 0; rp < RP; ++rp) {
                float2 v = upk(ar[rp]);  pp[2*rp]      = v.x; pp[2*rp + 1]      = v.y;
                float2 w = upk(az[rp]);  pp[16 + 2*rp] = w.x; pp[16 + 2*rp + 1] = w.y;
                float2 h = upk(an2[rp]); pp[32 + 2*rp] = h.x; pp[32 + 2*rp + 1] = h.y;
            }
        }
        __syncthreads();

        if (g == 0) {
            const float* pp = sh_part + tj * 49;
            float hnew[ROWS];
            #pragma unroll
            for (int rp = 0; rp < RP; ++rp) {
                float2 vr = upk(ar[rp]);  vr.x += pp[2*rp];      vr.y += pp[2*rp + 1];
                float2 vz = upk(az[rp]);  vz.x += pp[16 + 2*rp]; vz.y += pp[16 + 2*rp + 1];
                float2 vi = upk(an1[rp]);
                float2 vh = upk(an2[rp]); vh.x += pp[32 + 2*rp]; vh.y += pp[32 + 2*rp + 1];
                float r0 = sigmoidf_(vr.x), r1 = sigmoidf_(vr.y);
                float z0 = sigmoidf_(vz.x), z1 = sigmoidf_(vz.y);
                float n0 = tanhf_(vi.x + r0 * vh.x);
                float n1 = tanhf_(vi.y + r1 * vh.y);
                float o0 = sh_h[tj * PAD + 2 * rp];
                float o1 = sh_h[tj * PAD + 2 * rp + 1];
                hnew[2*rp]     = (1.f - z0) * n0 + z0 * o0;
                hnew[2*rp + 1] = (1.f - z1) * n1 + z1 * o1;
            }
            size_t base = ((size_t)row0 * TDIM + step) * HDIM + tj;
            #pragma unroll
            for (int r = 0; r < ROWS; ++r) {
                sh_h[tj * PAD + r] = hnew[r];
                g_hsh[base + (size_t)r * TDIM * HDIM] = __float2half_rn(hnew[r]);
            }
            // fused A/C partials (fp32, warp-reduced)
            float pa[ROWS], pc[ROWS];
            #pragma unroll
            for (int r = 0; r < ROWS; ++r) { pa[r] = hnew[r] * wqv; pc[r] = hnew[r] * bqv; }
            #pragma unroll
            for (int off = 16; off; off >>= 1) {
                #pragma unroll
                for (int r = 0; r < ROWS; ++r) {
                    pa[r] += __shfl_xor_sync(0xffffffffu, pa[r], off);
                    pc[r] += __shfl_xor_sync(0xffffffffu, pc[r], off);
                }
            }
            if ((tj & 31) == 0) {
                #pragma unroll
                for (int r = 0; r < ROWS; ++r) {
                    sh_ac[wp * 32 + r * 2]     = pa[r];
                    sh_ac[wp * 32 + r * 2 + 1] = pc[r];
                }
            }
        } else if (step + 1 < TDIM) {
            for (int i = tj; i < ROWS * FDIM; i += 256) {
                int r = i >> 6, f = i & 63;
                xn[f * PAD + r] = x[((size_t)(row0 + r) * TDIM + (step + 1)) * FDIM + f];
            }
        }
        __syncthreads();
        if (t < 32) {
            int r = t >> 1, isC = t & 1;
            float s = 0.f;
            #pragma unroll
            for (int w = 0; w < 8; ++w) s += sh_ac[w * 32 + r * 2 + isC];
            if (isC) g_C[(row0 + r) * TDIM + step] = s;
            else     g_A[(row0 + r) * TDIM + step] = s;
        }
    }
}

// ---------------- decoder: 512 threads, split-K, fp16 hs for ctx ----------------
// smem float offsets
#define D_CTX  0                     // 256*PAD = 4608
#define D_A    4608                  // 16*128  = 2048
#define D_C    6656
#define D_W    8704
#define D_PART 10752                 // 256*48 = 12288
#define D_PREV 23040                 // 16
#define D_RED  23056                 // 16*16 = 256
#define DEC_SMEM_FLOATS 23312        // 93248 bytes

__global__ void __launch_bounds__(512, 1)
decoder_kernel(const float* __restrict__ x,
               const float* __restrict__ dWih, const float* __restrict__ dbih,
               const float* __restrict__ dbhh,
               const float* __restrict__ fc1b, const float* __restrict__ fc2W,
               const float* __restrict__ fc2b, float* __restrict__ out) {
    extern __shared__ float dsm[];
    float* sh_ctx  = dsm + D_CTX;
    float* sh_A    = dsm + D_A;
    float* sh_C    = dsm + D_C;
    float* sh_w    = dsm + D_W;
    float* sh_part = dsm + D_PART;
    float* sh_prev = dsm + D_PREV;
    float* sh_red  = dsm + D_RED;

    const int t = threadIdx.x;
    const int row0 = blockIdx.x * ROWS;
    const int wp = t >> 5, lane = t & 31;
    const int g2 = t >> 8, tj = t & 255;
    const int qg = t >> 7, h2 = t & 127;

    for (int i = t; i < ROWS * TDIM; i += 512) {
        int r = i >> 7, tt = i & 127;
        sh_A[r * TDIM + tt] = g_A[(row0 + r) * TDIM + tt];
        sh_C[r * TDIM + tt] = g_C[(row0 + r) * TDIM + tt];
    }
    if (t < ROWS)
        sh_prev[t] = x[((size_t)(row0 + t) * TDIM + (TDIM - 1)) * FDIM + 0];

    const float dbr  = dbih[tj]          + dbhh[tj];
    const float dbz  = dbih[tj + HDIM]   + dbhh[tj + HDIM];
    const float dbin = dbih[tj + 2*HDIM];
    const float dbhn = dbhh[tj + 2*HDIM];
    const float wir  = dWih[tj], wiz = dWih[tj + HDIM], win = dWih[tj + 2*HDIM];
    const float f1b  = fc1b[tj];
    const float f2w  = fc2W[tj];
    const float f2b  = fc2b[0];
    const float scale = 0.0625f;   // 1/sqrt(256)
    __syncthreads();

    for (int step = 0; step < OUTL; ++step) {
        // ---- scores + softmax: one warp per row ----
        {
            int r = wp;
            float pv = sh_prev[r];
            float sv[4], m = -1e30f;
            #pragma unroll
            for (int i = 0; i < 4; ++i) {
                int tt = lane + 32 * i;
                float s = (pv * sh_A[r * TDIM + tt] + sh_C[r * TDIM + tt]) * scale;
                sv[i] = s; m = fmaxf(m, s);
            }
            #pragma unroll
            for (int off = 16; off; off >>= 1) m = fmaxf(m, __shfl_xor_sync(0xffffffffu, m, off));
            float sum = 0.f;
            #pragma unroll
            for (int i = 0; i < 4; ++i) { sv[i] = __expf(sv[i] - m); sum += sv[i]; }
            #pragma unroll
            for (int off = 16; off; off >>= 1) sum += __shfl_xor_sync(0xffffffffu, sum, off);
            float inv = __fdividef(1.f, sum);
            #pragma unroll
            for (int i = 0; i < 4; ++i) sh_w[r * TDIM + lane + 32 * i] = sv[i] * inv;
        }
        __syncthreads();

        // ---- ctx: thread covers 4 rows (qg) x 2 h (2*h2, 2*h2+1), fp16x2 loads ----
        {
            float a0x = 0.f, a0y = 0.f, a1x = 0.f, a1y = 0.f;
            float a2x = 0.f, a2y = 0.f, a3x = 0.f, a3y = 0.f;
            const __half* hb =
                g_hsh + ((size_t)(row0 + qg * 4) * TDIM) * HDIM + 2 * h2;
            const size_t rstride = (size_t)TDIM * HDIM;
            #pragma unroll 2
            for (int tt = 0; tt < TDIM; ++tt) {
                const __half* hp = hb + (size_t)tt * HDIM;
                __half2 v0 = *reinterpret_cast<const __half2*>(hp);
                __half2 v1 = *reinterpret_cast<const __half2*>(hp + rstride);
                __half2 v2 = *reinterpret_cast<const __half2*>(hp + 2 * rstride);
                __half2 v3 = *reinterpret_cast<const __half2*>(hp + 3 * rstride);
                float w0 = sh_w[(qg * 4 + 0) * TDIM + tt];
                float w1 = sh_w[(qg * 4 + 1) * TDIM + tt];
                float w2 = sh_w[(qg * 4 + 2) * TDIM + tt];
                float w3 = sh_w[(qg * 4 + 3) * TDIM + tt];
                float2 f0 = __half22float2(v0);
                float2 f1 = __half22float2(v1);
                float2 f2 = __half22float2(v2);
                float2 f3 = __half22float2(v3);
                a0x = fmaf(w0, f0.x, a0x); a0y = fmaf(w0, f0.y, a0y);
                a1x = fmaf(w1, f1.x, a1x); a1y = fmaf(w1, f1.y, a1y);
                a2x = fmaf(w2, f2.x, a2x); a2y = fmaf(w2, f2.y, a2y);
                a3x = fmaf(w3, f3.x, a3x); a3y = fmaf(w3, f3.y, a3y);
            }
            int hx = 2 * h2, r0 = qg * 4;
            sh_ctx[hx * PAD + r0 + 0] = a0x; sh_ctx[(hx + 1) * PAD + r0 + 0] = a0y;
            sh_ctx[hx * PAD + r0 + 1] = a1x; sh_ctx[(hx + 1) * PAD + r0 + 1] = a1y;
            sh_ctx[hx * PAD + r0 + 2] = a2x; sh_ctx[(hx + 1) * PAD + r0 + 2] = a2y;
            sh_ctx[hx * PAD + r0 + 3] = a3x; sh_ctx[(hx + 1) * PAD + r0 + 3] = a3y;
        }
        __syncthreads();

        // ---- GRU cell (split-K: g2=0 -> k 0..127, g2=1 -> k 128..255) ----
        u64 ar[RP], az[RP], ahn[RP], ain[RP];
        if (g2 == 0) {
            #pragma unroll
            for (int rp = 0; rp < RP; ++rp) {
                float p0 = sh_prev[2*rp], p1 = sh_prev[2*rp + 1];
                ar[rp]  = pk2p(fmaf(p0, wir, dbr),  fmaf(p1, wir, dbr));
                az[rp]  = pk2p(fmaf(p0, wiz, dbz),  fmaf(p1, wiz, dbz));
                ain[rp] = pk2p(fmaf(p0, win, dbin), fmaf(p1, win, dbin));
                ahn[rp] = pk2(dbhn);
            }
        } else {
            u64 z0 = pk2(0.f);
            #pragma unroll
            for (int rp = 0; rp < RP; ++rp) { ar[rp]=z0; az[rp]=z0; ahn[rp]=z0; ain[rp]=z0; }
        }
        {
            const int k0 = g2 * 128;
            #pragma unroll 2
            for (int kk = 0; kk < 128; ++kk) {
                int k = k0 + kk;
                float2 w  = g_DWrz[k * 256 + tj];
                float  wn = g_DWn [k * 256 + tj];
                u64 wr = pk2(w.x), wzv = pk2(w.y), wn2 = pk2(wn);
                #pragma unroll
                for (int rp = 0; rp < RP; ++rp) {
                    u64 cv = lds2(&sh_ctx[k * PAD + 2*rp]);
                    fma2(ar[rp],  cv, wr);
                    fma2(az[rp],  cv, wzv);
                    fma2(ahn[rp], cv, wn2);
                }
            }
        }
        if (g2 == 1) {
            float* pp = sh_part + tj * 48;
            #pragma unroll
            for (int rp = 0; rp < RP; ++rp) {
                float2 v = upk(ar[rp]);  pp[2*rp]      = v.x; pp[2*rp + 1]      = v.y;
                float2 w = upk(az[rp]);  pp[16 + 2*rp] = w.x; pp[16 + 2*rp + 1] = w.y;
                float2 h = upk(ahn[rp]); pp[32 + 2*rp] = h.x; pp[32 + 2*rp + 1] = h.y;
            }
        }
        __syncthreads();

        if (g2 == 0) {
            const float* pp = sh_part + tj * 48;
            float hd[ROWS];
            #pragma unroll
            for (int rp = 0; rp < RP; ++rp) {
                float2 vr = upk(ar[rp]);  vr.x += pp[2*rp];      vr.y += pp[2*rp + 1];
                float2 vz = upk(az[rp]);  vz.x += pp[16 + 2*rp]; vz.y += pp[16 + 2*rp + 1];
                float2 vi = upk(ain[rp]);
                float2 vh = upk(ahn[rp]); vh.x += pp[32 + 2*rp]; vh.y += pp[32 + 2*rp + 1];
                float r0 = sigmoidf_(vr.x), r1 = sigmoidf_(vr.y);
                float z0 = sigmoidf_(vz.x), z1 = sigmoidf_(vz.y);
                float n0 = tanhf_(vi.x + r0 * vh.x);
                float n1 = tanhf_(vi.y + r1 * vh.y);
                float c0 = sh_ctx[tj * PAD + 2*rp];
                float c1 = sh_ctx[tj * PAD + 2*rp + 1];
                hd[2*rp]     = (1.f - z0) * n0 + z0 * c0;
                hd[2*rp + 1] = (1.f - z1) * n1 + z1 * c1;
            }
            #pragma unroll
            for (int r = 0; r < ROWS; ++r) sh_ctx[tj * PAD + r] = hd[r];
        }
        __syncthreads();

        // ---- fc1 (relu), split-K ----
        u64 a1[RP];
        {
            u64 b1 = (g2 == 0) ? pk2(f1b) : pk2(0.f);
            #pragma unroll
            for (int rp = 0; rp < RP; ++rp) a1[rp] = b1;
            const int k0 = g2 * 128;
            #pragma unroll 2
            for (int kk = 0; kk < 128; ++kk) {
                int k = k0 + kk;
                u64 wf = pk2(g_WtFc1[k * FCH + tj]);
                #pragma unroll
                for (int rp = 0; rp < RP; ++rp) {
                    u64 hv = lds2(&sh_ctx[k * PAD + 2*rp]);
                    fma2(a1[rp], hv, wf);
                }
            }
        }
        if (g2 == 1) {
            float* pp = sh_part + tj * 48;
            #pragma unroll
            for (int rp = 0; rp < RP; ++rp) {
                float2 v = upk(a1[rp]);
                pp[2*rp] = v.x; pp[2*rp + 1] = v.y;
            }
        }
        __syncthreads();

        if (g2 == 0) {
            const float* pp = sh_part + tj * 48;
            float p[ROWS];
            #pragma unroll
            for (int rp = 0; rp < RP; ++rp) {
                float2 v = upk(a1[rp]);
                p[2*rp]     = fmaxf(v.x + pp[2*rp],     0.f) * f2w;
                p[2*rp + 1] = fmaxf(v.y + pp[2*rp + 1], 0.f) * f2w;
            }
            #pragma unroll
            for (int off = 16; off; off >>= 1) {
                #pragma unroll
                for (int r = 0; r < ROWS; ++r)
                    p[r] += __shfl_xor_sync(0xffffffffu, p[r], off);
            }
            if (lane == 0) {
                #pragma unroll
                for (int r = 0; r < ROWS; ++r) sh_red[wp * ROWS + r] = p[r];
            }
        }
        __syncthreads();
        if (t < ROWS) {
            float s = f2b;
            #pragma unroll
            for (int w = 0; w < 8; ++w) s += sh_red[w * ROWS + t];
            out[(size_t)(row0 + t) * OUTL + step] = s;
            sh_prev[t] = s;
        }
        __syncthreads();
    }
}

// ---------------- launch ----------------
extern "C" void kernel_launch(void* const* d_in, const int* in_sizes, int n_in,
                              void* d_out, int out_size) {
    (void)in_sizes; (void)n_in; (void)out_size;
    const float* x       = (const float*)d_in[0];
    const float* h0      = (const float*)d_in[1];
    const float* enc_Wih = (const float*)d_in[2];
    const float* enc_Whh = (const float*)d_in[3];
    const float* enc_bih = (const float*)d_in[4];
    const float* enc_bhh = (const float*)d_in[5];
    const float* dec_Wih = (const float*)d_in[6];
    const float* dec_Whh = (const float*)d_in[7];
    const float* dec_bih = (const float*)d_in[8];
    const float* dec_bhh = (const float*)d_in[9];
    const float* attn_Wq = (const float*)d_in[10];
    const float* attn_bq = (const float*)d_in[11];
    const float* fc1_W   = (const float*)d_in[12];
    const float* fc1_b   = (const float*)d_in[13];
    const float* fc2_W   = (const float*)d_in[14];
    const float* fc2_b   = (const float*)d_in[15];
    float* out = (float*)d_out;

    const int enc_smem = ENC_SMEM_FLOATS * (int)sizeof(float);   // 177152 B
    const int dec_smem = DEC_SMEM_FLOATS * (int)sizeof(float);   // 93248 B
    cudaFuncSetAttribute(encoder_kernel,
                         cudaFuncAttributeMaxDynamicSharedMemorySize, enc_smem);
    cudaFuncSetAttribute(decoder_kernel,
                         cudaFuncAttributeMaxDynamicSharedMemorySize, dec_smem);

    prep_kernel<<<(320 * 256 + NTHR - 1) / NTHR, NTHR>>>(enc_Wih, enc_Whh, dec_Whh, fc1_W);
    encoder_kernel<<<NCTA, 512, enc_smem>>>(x, h0, enc_bih, enc_bhh, attn_Wq, attn_bq);
    decoder_kernel<<<NCTA, 512, dec_smem>>>(x, dec_Wih, dec_bih, dec_bhh,
                                            fc1_b, fc2_W, fc2_b, out);
}

// round 11
// speedup vs baseline: 1.8792x; 1.3239x over previous
#include <cuda_runtime.h>
#include <cuda_fp16.h>

#define BDIM 2048
#define TDIM 128
#define FDIM 64
#define HDIM 256
#define G3   768
#define OUTL 32
#define FCH  256

#define ROWS 16
#define RP   8
#define NTHR 256
#define NCTA (BDIM / ROWS)   // 128
#define PAD  18

typedef unsigned long long u64;

// ---------------- scratch (__device__ globals; no allocations) ----------------
__device__ __half g_hsh[(size_t)BDIM * TDIM * HDIM];  // 128 MB fp16 [b][t][h]
__device__ float  g_A[BDIM * TDIM];
__device__ float  g_C[BDIM * TDIM];
__device__ float4 g_W4[320 * 256];     // encoder cat [idx][j]: (wr, wz, wn, 0)
__device__ float2 g_DWrz[256 * 256];   // decoder Whh [k][j]
__device__ float  g_DWn [256 * 256];
__device__ float  g_WtFc1[HDIM * FCH]; // [k][j]

// ---------------- helpers ----------------
__device__ __forceinline__ u64 pk2(float v) {
    u64 r; unsigned int u = __float_as_uint(v);
    asm("mov.b64 %0, {%1, %2};" : "=l"(r) : "r"(u), "r"(u));
    return r;
}
__device__ __forceinline__ u64 pk2p(float a, float b) {
    u64 r;
    asm("mov.b64 %0, {%1, %2};" : "=l"(r)
        : "r"(__float_as_uint(a)), "r"(__float_as_uint(b)));
    return r;
}
__device__ __forceinline__ float2 upk(u64 v) {
    unsigned int lo, hi;
    asm("mov.b64 {%0, %1}, %2;" : "=r"(lo), "=r"(hi) : "l"(v));
    return make_float2(__uint_as_float(lo), __uint_as_float(hi));
}
__device__ __forceinline__ void fma2(u64& acc, u64 a, u64 b) {
    asm("fma.rn.f32x2 %0, %1, %2, %0;" : "+l"(acc) : "l"(a), "l"(b));
}
__device__ __forceinline__ u64 lds2(const float* p) {
    return *reinterpret_cast<const u64*>(p);
}
__device__ __forceinline__ float sigmoidf_(float x) {
    float e = __expf(-x);
    return __fdividef(1.0f, 1.0f + e);
}
__device__ __forceinline__ float tanhf_(float x) {
    float xx = fminf(fmaxf(x, -15.f), 15.f);
    float e = __expf(2.f * xx);
    return __fdividef(e - 1.f, e + 1.f);
}

// ---------------- prep: weight repack ----------------
__global__ void prep_kernel(const float* __restrict__ encWih,
                            const float* __restrict__ encWhh,
                            const float* __restrict__ decWhh,
                            const float* __restrict__ fc1W) {
    int i = blockIdx.x * blockDim.x + threadIdx.x;
    if (i < 320 * 256) {
        int row = i >> 8, j = i & 255;
        float wr, wz, wn;
        if (row < 64) {
            int f = row;
            wr = encWih[j * FDIM + f];
            wz = encWih[(j + HDIM) * FDIM + f];
            wn = encWih[(j + 2 * HDIM) * FDIM + f];
        } else {
            int k = row - 64;
            wr = encWhh[j * HDIM + k];
            wz = encWhh[(j + HDIM) * HDIM + k];
            wn = encWhh[(j + 2 * HDIM) * HDIM + k];
        }
        g_W4[i] = make_float4(wr, wz, wn, 0.f);
    }
    if (i < 256 * 256) {
        int k = i >> 8, j = i & 255;
        g_DWrz[i] = make_float2(decWhh[j * HDIM + k], decWhh[(j + HDIM) * HDIM + k]);
        g_DWn[i]  = decWhh[(j + 2 * HDIM) * HDIM + k];
        g_WtFc1[k * FCH + j] = fc1W[j * HDIM + k];
    }
}

// ---------------- encoder: 512 threads, split-K, direct float4 LDG, fused A/C ----------------
// smem float offsets
#define E_H    0                     // 256*PAD = 4608
#define E_X0   4608                  // 64*PAD  = 1152
#define E_X1   5760
#define E_PART 6912                  // 256*49  = 12544
#define E_AC   19456                 // 8 warps * 16 rows * 2 = 256 f
#define ENC_SMEM_FLOATS 19712        // 78848 bytes

__global__ void __launch_bounds__(512, 1)
encoder_kernel(const float* __restrict__ x, const float* __restrict__ h0,
               const float* __restrict__ bih, const float* __restrict__ bhh,
               const float* __restrict__ attnWq, const float* __restrict__ attnBq) {
    extern __shared__ float sm[];
    float* sh_h    = sm + E_H;
    float* sh_x0   = sm + E_X0;
    float* sh_x1   = sm + E_X1;
    float* sh_part = sm + E_PART;
    float* sh_ac   = sm + E_AC;

    const int t  = threadIdx.x;
    const int g  = t >> 8;
    const int tj = t & 255;
    const int wp = tj >> 5;
    const int row0 = blockIdx.x * ROWS;

    const float bias_r  = bih[tj]            + bhh[tj];
    const float bias_z  = bih[tj + HDIM]     + bhh[tj + HDIM];
    const float bias_in = bih[tj + 2 * HDIM];
    const float bias_hn = bhh[tj + 2 * HDIM];
    const float wqv = attnWq[tj];
    const float bqv = attnBq[tj];

    for (int i = t; i < ROWS * HDIM; i += 512) {
        int r = i >> 8, k = i & 255;
        sh_h[k * PAD + r] = h0[(size_t)(row0 + r) * HDIM + k];
    }
    for (int i = t; i < ROWS * FDIM; i += 512) {
        int r = i >> 6, f = i & 63;
        sh_x0[f * PAD + r] = x[((size_t)(row0 + r) * TDIM + 0) * FDIM + f];
    }
    __syncthreads();

    const float4* __restrict__ W4 = g_W4;

    for (int step = 0; step < TDIM; ++step) {
        float* xb = (step & 1) ? sh_x1 : sh_x0;
        float* xn = (step & 1) ? sh_x0 : sh_x1;

        u64 ar[RP], az[RP], an1[RP], an2[RP];
        if (g == 0) {
            u64 br2 = pk2(bias_r), bz2 = pk2(bias_z), bi2 = pk2(bias_in), bh2 = pk2(bias_hn);
            #pragma unroll
            for (int rp = 0; rp < RP; ++rp) { ar[rp]=br2; az[rp]=bz2; an1[rp]=bi2; an2[rp]=bh2; }
            // x projection (f = 0..63): wn accumulates into i_n (an1)
            #pragma unroll 4
            for (int f = 0; f < FDIM; ++f) {
                float4 w = W4[f * 256 + tj];
                u64 wr2 = pk2(w.x), wz2 = pk2(w.y), wn2 = pk2(w.z);
                #pragma unroll
                for (int rp = 0; rp < RP; ++rp) {
                    u64 v = lds2(&xb[f * PAD + 2 * rp]);
                    fma2(ar[rp],  v, wr2);
                    fma2(az[rp],  v, wz2);
                    fma2(an1[rp], v, wn2);
                }
            }
            // h projection k = 0..95: wn accumulates into h_n (an2)
            #pragma unroll 4
            for (int k = 0; k < 96; ++k) {
                float4 w = W4[(64 + k) * 256 + tj];
                u64 wr2 = pk2(w.x), wz2 = pk2(w.y), wn2 = pk2(w.z);
                #pragma unroll
                for (int rp = 0; rp < RP; ++rp) {
                    u64 v = lds2(&sh_h[k * PAD + 2 * rp]);
                    fma2(ar[rp],  v, wr2);
                    fma2(az[rp],  v, wz2);
                    fma2(an2[rp], v, wn2);
                }
            }
        } else {
            u64 z0 = pk2(0.f);
            #pragma unroll
            for (int rp = 0; rp < RP; ++rp) { ar[rp]=z0; az[rp]=z0; an1[rp]=z0; an2[rp]=z0; }
            // h projection k = 96..255
            #pragma unroll 4
            for (int k = 96; k < 256; ++k) {
                float4 w = W4[(64 + k) * 256 + tj];
                u64 wr2 = pk2(w.x), wz2 = pk2(w.y), wn2 = pk2(w.z);
                #pragma unroll
                for (int rp = 0; rp < RP; ++rp) {
                    u64 v = lds2(&sh_h[k * PAD + 2 * rp]);
                    fma2(ar[rp],  v, wr2);
                    fma2(az[rp],  v, wz2);
                    fma2(an2[rp], v, wn2);
                }
            }
            // publish partials
            float* pp = sh_part + tj * 49;
            #pragma unroll
            for (int rp = 0; rp < RP; ++rp) {
                float2 v = upk(ar[rp]);  pp[2*rp]      = v.x; pp[2*rp + 1]      = v.y;
                float2 w = upk(az[rp]);  pp[16 + 2*rp] = w.x; pp[16 + 2*rp + 1] = w.y;
                float2 h = upk(an2[rp]); pp[32 + 2*rp] = h.x; pp[32 + 2*rp + 1] = h.y;
            }
        }
        __syncthreads();

        if (g == 0) {
            const float* pp = sh_part + tj * 49;
            float hnew[ROWS];
            #pragma unroll
            for (int rp = 0; rp < RP; ++rp) {
                float2 vr = upk(ar[rp]);  vr.x += pp[2*rp];      vr.y += pp[2*rp + 1];
                float2 vz = upk(az[rp]);  vz.x += pp[16 + 2*rp]; vz.y += pp[16 + 2*rp + 1];
                float2 vi = upk(an1[rp]);
                float2 vh = upk(an2[rp]); vh.x += pp[32 + 2*rp]; vh.y += pp[32 + 2*rp + 1];
                float r0 = sigmoidf_(vr.x), r1 = sigmoidf_(vr.y);
                float z0 = sigmoidf_(vz.x), z1 = sigmoidf_(vz.y);
                float n0 = tanhf_(vi.x + r0 * vh.x);
                float n1 = tanhf_(vi.y + r1 * vh.y);
                float o0 = sh_h[tj * PAD + 2 * rp];
                float o1 = sh_h[tj * PAD + 2 * rp + 1];
                hnew[2*rp]     = (1.f - z0) * n0 + z0 * o0;
                hnew[2*rp + 1] = (1.f - z1) * n1 + z1 * o1;
            }
            size_t base = ((size_t)row0 * TDIM + step) * HDIM + tj;
            #pragma unroll
            for (int r = 0; r < ROWS; ++r) {
                sh_h[tj * PAD + r] = hnew[r];
                g_hsh[base + (size_t)r * TDIM * HDIM] = __float2half_rn(hnew[r]);
            }
            // fused A/C partials (fp32, warp-reduced)
            float pa[ROWS], pc[ROWS];
            #pragma unroll
            for (int r = 0; r < ROWS; ++r) { pa[r] = hnew[r] * wqv; pc[r] = hnew[r] * bqv; }
            #pragma unroll
            for (int off = 16; off; off >>= 1) {
                #pragma unroll
                for (int r = 0; r < ROWS; ++r) {
                    pa[r] += __shfl_xor_sync(0xffffffffu, pa[r], off);
                    pc[r] += __shfl_xor_sync(0xffffffffu, pc[r], off);
                }
            }
            if ((tj & 31) == 0) {
                #pragma unroll
                for (int r = 0; r < ROWS; ++r) {
                    sh_ac[wp * 32 + r * 2]     = pa[r];
                    sh_ac[wp * 32 + r * 2 + 1] = pc[r];
                }
            }
        } else if (step + 1 < TDIM) {
            for (int i = tj; i < ROWS * FDIM; i += 256) {
                int r = i >> 6, f = i & 63;
                xn[f * PAD + r] = x[((size_t)(row0 + r) * TDIM + (step + 1)) * FDIM + f];
            }
        }
        __syncthreads();
        if (t < 32) {
            int r = t >> 1, isC = t & 1;
            float s = 0.f;
            #pragma unroll
            for (int w = 0; w < 8; ++w) s += sh_ac[w * 32 + r * 2 + isC];
            if (isC) g_C[(row0 + r) * TDIM + step] = s;
            else     g_A[(row0 + r) * TDIM + step] = s;
        }
    }
}

// ---------------- decoder: 512 threads, split-K, fp16 hs for ctx ----------------
// smem float offsets
#define D_CTX  0                     // 256*PAD = 4608
#define D_A    4608                  // 16*128  = 2048
#define D_C    6656
#define D_W    8704
#define D_PART 10752                 // 256*48 = 12288
#define D_PREV 23040                 // 16
#define D_RED  23056                 // 16*16 = 256
#define DEC_SMEM_FLOATS 23312        // 93248 bytes

__global__ void __launch_bounds__(512, 1)
decoder_kernel(const float* __restrict__ x,
               const float* __restrict__ dWih, const float* __restrict__ dbih,
               const float* __restrict__ dbhh,
               const float* __restrict__ fc1b, const float* __restrict__ fc2W,
               const float* __restrict__ fc2b, float* __restrict__ out) {
    extern __shared__ float dsm[];
    float* sh_ctx  = dsm + D_CTX;
    float* sh_A    = dsm + D_A;
    float* sh_C    = dsm + D_C;
    float* sh_w    = dsm + D_W;
    float* sh_part = dsm + D_PART;
    float* sh_prev = dsm + D_PREV;
    float* sh_red  = dsm + D_RED;

    const int t = threadIdx.x;
    const int row0 = blockIdx.x * ROWS;
    const int wp = t >> 5, lane = t & 31;
    const int g2 = t >> 8, tj = t & 255;
    const int qg = t >> 7, h2 = t & 127;

    for (int i = t; i < ROWS * TDIM; i += 512) {
        int r = i >> 7, tt = i & 127;
        sh_A[r * TDIM + tt] = g_A[(row0 + r) * TDIM + tt];
        sh_C[r * TDIM + tt] = g_C[(row0 + r) * TDIM + tt];
    }
    if (t < ROWS)
        sh_prev[t] = x[((size_t)(row0 + t) * TDIM + (TDIM - 1)) * FDIM + 0];

    const float dbr  = dbih[tj]          + dbhh[tj];
    const float dbz  = dbih[tj + HDIM]   + dbhh[tj + HDIM];
    const float dbin = dbih[tj + 2*HDIM];
    const float dbhn = dbhh[tj + 2*HDIM];
    const float wir  = dWih[tj], wiz = dWih[tj + HDIM], win = dWih[tj + 2*HDIM];
    const float f1b  = fc1b[tj];
    const float f2w  = fc2W[tj];
    const float f2b  = fc2b[0];
    const float scale = 0.0625f;   // 1/sqrt(256)
    __syncthreads();

    for (int step = 0; step < OUTL; ++step) {
        // ---- scores + softmax: one warp per row ----
        {
            int r = wp;
            float pv = sh_prev[r];
            float sv[4], m = -1e30f;
            #pragma unroll
            for (int i = 0; i < 4; ++i) {
                int tt = lane + 32 * i;
                float s = (pv * sh_A[r * TDIM + tt] + sh_C[r * TDIM + tt]) * scale;
                sv[i] = s; m = fmaxf(m, s);
            }
            #pragma unroll
            for (int off = 16; off; off >>= 1) m = fmaxf(m, __shfl_xor_sync(0xffffffffu, m, off));
            float sum = 0.f;
            #pragma unroll
            for (int i = 0; i < 4; ++i) { sv[i] = __expf(sv[i] - m); sum += sv[i]; }
            #pragma unroll
            for (int off = 16; off; off >>= 1) sum += __shfl_xor_sync(0xffffffffu, sum, off);
            float inv = __fdividef(1.f, sum);
            #pragma unroll
            for (int i = 0; i < 4; ++i) sh_w[r * TDIM + lane + 32 * i] = sv[i] * inv;
        }
        __syncthreads();

        // ---- ctx: thread covers 4 rows (qg) x 2 h (2*h2, 2*h2+1), fp16x2 loads ----
        {
            float a0x = 0.f, a0y = 0.f, a1x = 0.f, a1y = 0.f;
            float a2x = 0.f, a2y = 0.f, a3x = 0.f, a3y = 0.f;
            const __half* hb =
                g_hsh + ((size_t)(row0 + qg * 4) * TDIM) * HDIM + 2 * h2;
            const size_t rstride = (size_t)TDIM * HDIM;
            #pragma unroll 2
            for (int tt = 0; tt < TDIM; ++tt) {
                const __half* hp = hb + (size_t)tt * HDIM;
                __half2 v0 = *reinterpret_cast<const __half2*>(hp);
                __half2 v1 = *reinterpret_cast<const __half2*>(hp + rstride);
                __half2 v2 = *reinterpret_cast<const __half2*>(hp + 2 * rstride);
                __half2 v3 = *reinterpret_cast<const __half2*>(hp + 3 * rstride);
                float w0 = sh_w[(qg * 4 + 0) * TDIM + tt];
                float w1 = sh_w[(qg * 4 + 1) * TDIM + tt];
                float w2 = sh_w[(qg * 4 + 2) * TDIM + tt];
                float w3 = sh_w[(qg * 4 + 3) * TDIM + tt];
                float2 f0 = __half22float2(v0);
                float2 f1 = __half22float2(v1);
                float2 f2 = __half22float2(v2);
                float2 f3 = __half22float2(v3);
                a0x = fmaf(w0, f0.x, a0x); a0y = fmaf(w0, f0.y, a0y);
                a1x = fmaf(w1, f1.x, a1x); a1y = fmaf(w1, f1.y, a1y);
                a2x = fmaf(w2, f2.x, a2x); a2y = fmaf(w2, f2.y, a2y);
                a3x = fmaf(w3, f3.x, a3x); a3y = fmaf(w3, f3.y, a3y);
            }
            int hx = 2 * h2, r0 = qg * 4;
            sh_ctx[hx * PAD + r0 + 0] = a0x; sh_ctx[(hx + 1) * PAD + r0 + 0] = a0y;
            sh_ctx[hx * PAD + r0 + 1] = a1x; sh_ctx[(hx + 1) * PAD + r0 + 1] = a1y;
            sh_ctx[hx * PAD + r0 + 2] = a2x; sh_ctx[(hx + 1) * PAD + r0 + 2] = a2y;
            sh_ctx[hx * PAD + r0 + 3] = a3x; sh_ctx[(hx + 1) * PAD + r0 + 3] = a3y;
        }
        __syncthreads();

        // ---- GRU cell (split-K: g2=0 -> k 0..127, g2=1 -> k 128..255) ----
        u64 ar[RP], az[RP], ahn[RP], ain[RP];
        if (g2 == 0) {
            #pragma unroll
            for (int rp = 0; rp < RP; ++rp) {
                float p0 = sh_prev[2*rp], p1 = sh_prev[2*rp + 1];
                ar[rp]  = pk2p(fmaf(p0, wir, dbr),  fmaf(p1, wir, dbr));
                az[rp]  = pk2p(fmaf(p0, wiz, dbz),  fmaf(p1, wiz, dbz));
                ain[rp] = pk2p(fmaf(p0, win, dbin), fmaf(p1, win, dbin));
                ahn[rp] = pk2(dbhn);
            }
        } else {
            u64 z0 = pk2(0.f);
            #pragma unroll
            for (int rp = 0; rp < RP; ++rp) { ar[rp]=z0; az[rp]=z0; ahn[rp]=z0; ain[rp]=z0; }
        }
        {
            const int k0 = g2 * 128;
            #pragma unroll 2
            for (int kk = 0; kk < 128; ++kk) {
                int k = k0 + kk;
                float2 w  = g_DWrz[k * 256 + tj];
                float  wn = g_DWn [k * 256 + tj];
                u64 wr = pk2(w.x), wzv = pk2(w.y), wn2 = pk2(wn);
                #pragma unroll
                for (int rp = 0; rp < RP; ++rp) {
                    u64 cv = lds2(&sh_ctx[k * PAD + 2*rp]);
                    fma2(ar[rp],  cv, wr);
                    fma2(az[rp],  cv, wzv);
                    fma2(ahn[rp], cv, wn2);
                }
            }
        }
        if (g2 == 1) {
            float* pp = sh_part + tj * 48;
            #pragma unroll
            for (int rp = 0; rp < RP; ++rp) {
                float2 v = upk(ar[rp]);  pp[2*rp]      = v.x; pp[2*rp + 1]      = v.y;
                float2 w = upk(az[rp]);  pp[16 + 2*rp] = w.x; pp[16 + 2*rp + 1] = w.y;
                float2 h = upk(ahn[rp]); pp[32 + 2*rp] = h.x; pp[32 + 2*rp + 1] = h.y;
            }
        }
        __syncthreads();

        if (g2 == 0) {
            const float* pp = sh_part + tj * 48;
            float hd[ROWS];
            #pragma unroll
            for (int rp = 0; rp < RP; ++rp) {
                float2 vr = upk(ar[rp]);  vr.x += pp[2*rp];      vr.y += pp[2*rp + 1];
                float2 vz = upk(az[rp]);  vz.x += pp[16 + 2*rp]; vz.y += pp[16 + 2*rp + 1];
                float2 vi = upk(ain[rp]);
                float2 vh = upk(ahn[rp]); vh.x += pp[32 + 2*rp]; vh.y += pp[32 + 2*rp + 1];
                float r0 = sigmoidf_(vr.x), r1 = sigmoidf_(vr.y);
                float z0 = sigmoidf_(vz.x), z1 = sigmoidf_(vz.y);
                float n0 = tanhf_(vi.x + r0 * vh.x);
                float n1 = tanhf_(vi.y + r1 * vh.y);
                float c0 = sh_ctx[tj * PAD + 2*rp];
                float c1 = sh_ctx[tj * PAD + 2*rp + 1];
                hd[2*rp]     = (1.f - z0) * n0 + z0 * c0;
                hd[2*rp + 1] = (1.f - z1) * n1 + z1 * c1;
            }
            #pragma unroll
            for (int r = 0; r < ROWS; ++r) sh_ctx[tj * PAD + r] = hd[r];
        }
        __syncthreads();

        // ---- fc1 (relu), split-K ----
        u64 a1[RP];
        {
            u64 b1 = (g2 == 0) ? pk2(f1b) : pk2(0.f);
            #pragma unroll
            for (int rp = 0; rp < RP; ++rp) a1[rp] = b1;
            const int k0 = g2 * 128;
            #pragma unroll 2
            for (int kk = 0; kk < 128; ++kk) {
                int k = k0 + kk;
                u64 wf = pk2(g_WtFc1[k * FCH + tj]);
                #pragma unroll
                for (int rp = 0; rp < RP; ++rp) {
                    u64 hv = lds2(&sh_ctx[k * PAD + 2*rp]);
                    fma2(a1[rp], hv, wf);
                }
            }
        }
        if (g2 == 1) {
            float* pp = sh_part + tj * 48;
            #pragma unroll
            for (int rp = 0; rp < RP; ++rp) {
                float2 v = upk(a1[rp]);
                pp[2*rp] = v.x; pp[2*rp + 1] = v.y;
            }
        }
        __syncthreads();

        if (g2 == 0) {
            const float* pp = sh_part + tj * 48;
            float p[ROWS];
            #pragma unroll
            for (int rp = 0; rp < RP; ++rp) {
                float2 v = upk(a1[rp]);
                p[2*rp]     = fmaxf(v.x + pp[2*rp],     0.f) * f2w;
                p[2*rp + 1] = fmaxf(v.y + pp[2*rp + 1], 0.f) * f2w;
            }
            #pragma unroll
            for (int off = 16; off; off >>= 1) {
                #pragma unroll
                for (int r = 0; r < ROWS; ++r)
                    p[r] += __shfl_xor_sync(0xffffffffu, p[r], off);
            }
            if (lane == 0) {
                #pragma unroll
                for (int r = 0; r < ROWS; ++r) sh_red[wp * ROWS + r] = p[r];
            }
        }
        __syncthreads();
        if (t < ROWS) {
            float s = f2b;
            #pragma unroll
            for (int w = 0; w < 8; ++w) s += sh_red[w * ROWS + t];
            out[(size_t)(row0 + t) * OUTL + step] = s;
            sh_prev[t] = s;
        }
        __syncthreads();
    }
}

// ---------------- launch ----------------
extern "C" void kernel_launch(void* const* d_in, const int* in_sizes, int n_in,
                              void* d_out, int out_size) {
    (void)in_sizes; (void)n_in; (void)out_size;
    const float* x       = (const float*)d_in[0];
    const float* h0      = (const float*)d_in[1];
    const float* enc_Wih = (const float*)d_in[2];
    const float* enc_Whh = (const float*)d_in[3];
    const float* enc_bih = (const float*)d_in[4];
    const float* enc_bhh = (const float*)d_in[5];
    const float* dec_Wih = (const float*)d_in[6];
    const float* dec_Whh = (const float*)d_in[7];
    const float* dec_bih = (const float*)d_in[8];
    const float* dec_bhh = (const float*)d_in[9];
    const float* attn_Wq = (const float*)d_in[10];
    const float* attn_bq = (const float*)d_in[11];
    const float* fc1_W   = (const float*)d_in[12];
    const float* fc1_b   = (const float*)d_in[13];
    const float* fc2_W   = (const float*)d_in[14];
    const float* fc2_b   = (const float*)d_in[15];
    float* out = (float*)d_out;

    const int enc_smem = ENC_SMEM_FLOATS * (int)sizeof(float);   // 78848 B
    const int dec_smem = DEC_SMEM_FLOATS * (int)sizeof(float);   // 93248 B
    cudaFuncSetAttribute(encoder_kernel,
                         cudaFuncAttributeMaxDynamicSharedMemorySize, enc_smem);
    cudaFuncSetAttribute(decoder_kernel,
                         cudaFuncAttributeMaxDynamicSharedMemorySize, dec_smem);

    prep_kernel<<<(320 * 256 + NTHR - 1) / NTHR, NTHR>>>(enc_Wih, enc_Whh, dec_Whh, fc1_W);
    encoder_kernel<<<NCTA, 512, enc_smem>>>(x, h0, enc_bih, enc_bhh, attn_Wq, attn_bq);
    decoder_kernel<<<NCTA, 512, dec_smem>>>(x, dec_Wih, dec_bih, dec_bhh,
                                            fc1_b, fc2_W, fc2_b, out);
}

// round 13
// speedup vs baseline: 1.8814x; 1.0012x over previous
#include <cuda_runtime.h>
#include <cuda_fp16.h>

#define BDIM 2048
#define TDIM 128
#define FDIM 64
#define HDIM 256
#define G3   768
#define OUTL 32
#define FCH  256

#define ROWS 16
#define RP   8
#define NTHR 256
#define NCTA (BDIM / ROWS)   // 128
#define PAD  18

typedef unsigned long long u64;

// ---------------- scratch (__device__ globals; no allocations) ----------------
__device__ __half g_hsh[(size_t)BDIM * TDIM * HDIM];  // 128 MB fp16 [b][t][h]
__device__ float  g_A[BDIM * TDIM];
__device__ float  g_C[BDIM * TDIM];
__device__ float4 g_W4[320 * 256];     // encoder cat [idx][j]: (wr, wz, wn, 0)
__device__ float2 g_DWrz[256 * 256];   // decoder Whh [k][j]
__device__ float  g_DWn [256 * 256];
__device__ float  g_WtFc1[HDIM * FCH]; // [k][j]

// ---------------- helpers ----------------
__device__ __forceinline__ u64 pk2(float v) {
    u64 r; unsigned int u = __float_as_uint(v);
    asm("mov.b64 %0, {%1, %2};" : "=l"(r) : "r"(u), "r"(u));
    return r;
}
__device__ __forceinline__ u64 pk2p(float a, float b) {
    u64 r;
    asm("mov.b64 %0, {%1, %2};" : "=l"(r)
        : "r"(__float_as_uint(a)), "r"(__float_as_uint(b)));
    return r;
}
__device__ __forceinline__ float2 upk(u64 v) {
    unsigned int lo, hi;
    asm("mov.b64 {%0, %1}, %2;" : "=r"(lo), "=r"(hi) : "l"(v));
    return make_float2(__uint_as_float(lo), __uint_as_float(hi));
}
__device__ __forceinline__ void fma2(u64& acc, u64 a, u64 b) {
    asm("fma.rn.f32x2 %0, %1, %2, %0;" : "+l"(acc) : "l"(a), "l"(b));
}
__device__ __forceinline__ u64 lds2(const float* p) {
    return *reinterpret_cast<const u64*>(p);
}
__device__ __forceinline__ float sigmoidf_(float x) {
    float e = __expf(-x);
    return __fdividef(1.0f, 1.0f + e);
}
__device__ __forceinline__ float tanhf_(float x) {
    float xx = fminf(fmaxf(x, -15.f), 15.f);
    float e = __expf(2.f * xx);
    return __fdividef(e - 1.f, e + 1.f);
}

// ---------------- prep: weight repack ----------------
__global__ void prep_kernel(const float* __restrict__ encWih,
                            const float* __restrict__ encWhh,
                            const float* __restrict__ decWhh,
                            const float* __restrict__ fc1W) {
    int i = blockIdx.x * blockDim.x + threadIdx.x;
    if (i < 320 * 256) {
        int row = i >> 8, j = i & 255;
        float wr, wz, wn;
        if (row < 64) {
            int f = row;
            wr = encWih[j * FDIM + f];
            wz = encWih[(j + HDIM) * FDIM + f];
            wn = encWih[(j + 2 * HDIM) * FDIM + f];
        } else {
            int k = row - 64;
            wr = encWhh[j * HDIM + k];
            wz = encWhh[(j + HDIM) * HDIM + k];
            wn = encWhh[(j + 2 * HDIM) * HDIM + k];
        }
        g_W4[i] = make_float4(wr, wz, wn, 0.f);
    }
    if (i < 256 * 256) {
        int k = i >> 8, j = i & 255;
        g_DWrz[i] = make_float2(decWhh[j * HDIM + k], decWhh[(j + HDIM) * HDIM + k]);
        g_DWn[i]  = decWhh[(j + 2 * HDIM) * HDIM + k];
        g_WtFc1[k * FCH + j] = fc1W[j * HDIM + k];
    }
}

// ---------------- encoder: 512 threads, split-K, direct float4 LDG, fused A/C ----------------
// smem float offsets
#define E_H    0                     // 256*PAD = 4608
#define E_X0   4608                  // 64*PAD  = 1152
#define E_X1   5760
#define E_PART 6912                  // 256*49  = 12544
#define E_AC   19456                 // 8 warps * 16 rows * 2 = 256 f
#define ENC_SMEM_FLOATS 19712        // 78848 bytes

__global__ void __launch_bounds__(512, 1)
encoder_kernel(const float* __restrict__ x, const float* __restrict__ h0,
               const float* __restrict__ bih, const float* __restrict__ bhh,
               const float* __restrict__ attnWq, const float* __restrict__ attnBq) {
    extern __shared__ float sm[];
    float* sh_h    = sm + E_H;
    float* sh_x0   = sm + E_X0;
    float* sh_x1   = sm + E_X1;
    float* sh_part = sm + E_PART;
    float* sh_ac   = sm + E_AC;

    const int t  = threadIdx.x;
    const int g  = t >> 8;
    const int tj = t & 255;
    const int wp = tj >> 5;
    const int row0 = blockIdx.x * ROWS;

    const float bias_r  = bih[tj]            + bhh[tj];
    const float bias_z  = bih[tj + HDIM]     + bhh[tj + HDIM];
    const float bias_in = bih[tj + 2 * HDIM];
    const float bias_hn = bhh[tj + 2 * HDIM];
    const float wqv = attnWq[tj];
    const float bqv = attnBq[tj];

    for (int i = t; i < ROWS * HDIM; i += 512) {
        int r = i >> 8, k = i & 255;
        sh_h[k * PAD + r] = h0[(size_t)(row0 + r) * HDIM + k];
    }
    for (int i = t; i < ROWS * FDIM; i += 512) {
        int r = i >> 6, f = i & 63;
        sh_x0[f * PAD + r] = x[((size_t)(row0 + r) * TDIM + 0) * FDIM + f];
    }
    __syncthreads();

    const float4* __restrict__ W4 = g_W4;

    for (int step = 0; step < TDIM; ++step) {
        float* xb = (step & 1) ? sh_x1 : sh_x0;
        float* xn = (step & 1) ? sh_x0 : sh_x1;

        u64 ar[RP], az[RP], an1[RP], an2[RP];
        if (g == 0) {
            u64 br2 = pk2(bias_r), bz2 = pk2(bias_z), bi2 = pk2(bias_in), bh2 = pk2(bias_hn);
            #pragma unroll
            for (int rp = 0; rp < RP; ++rp) { ar[rp]=br2; az[rp]=bz2; an1[rp]=bi2; an2[rp]=bh2; }
            // x projection (f = 0..63): wn accumulates into i_n (an1)
            #pragma unroll 4
            for (int f = 0; f < FDIM; ++f) {
                float4 w = W4[f * 256 + tj];
                u64 wr2 = pk2(w.x), wz2 = pk2(w.y), wn2 = pk2(w.z);
                #pragma unroll
                for (int rp = 0; rp < RP; ++rp) {
                    u64 v = lds2(&xb[f * PAD + 2 * rp]);
                    fma2(ar[rp],  v, wr2);
                    fma2(az[rp],  v, wz2);
                    fma2(an1[rp], v, wn2);
                }
            }
            // h projection k = 0..95: wn accumulates into h_n (an2)
            #pragma unroll 4
            for (int k = 0; k < 96; ++k) {
                float4 w = W4[(64 + k) * 256 + tj];
                u64 wr2 = pk2(w.x), wz2 = pk2(w.y), wn2 = pk2(w.z);
                #pragma unroll
                for (int rp = 0; rp < RP; ++rp) {
                    u64 v = lds2(&sh_h[k * PAD + 2 * rp]);
                    fma2(ar[rp],  v, wr2);
                    fma2(az[rp],  v, wz2);
                    fma2(an2[rp], v, wn2);
                }
            }
        } else {
            u64 z0 = pk2(0.f);
            #pragma unroll
            for (int rp = 0; rp < RP; ++rp) { ar[rp]=z0; az[rp]=z0; an1[rp]=z0; an2[rp]=z0; }
            // h projection k = 96..255
            #pragma unroll 4
            for (int k = 96; k < 256; ++k) {
                float4 w = W4[(64 + k) * 256 + tj];
                u64 wr2 = pk2(w.x), wz2 = pk2(w.y), wn2 = pk2(w.z);
                #pragma unroll
                for (int rp = 0; rp < RP; ++rp) {
                    u64 v = lds2(&sh_h[k * PAD + 2 * rp]);
                    fma2(ar[rp],  v, wr2);
                    fma2(az[rp],  v, wz2);
                    fma2(an2[rp], v, wn2);
                }
            }
            // publish partials
            float* pp = sh_part + tj * 49;
            #pragma unroll
            for (int rp = 0; rp < RP; ++rp) {
                float2 v = upk(ar[rp]);  pp[2*rp]      = v.x; pp[2*rp + 1]      = v.y;
                float2 w = upk(az[rp]);  pp[16 + 2*rp] = w.x; pp[16 + 2*rp + 1] = w.y;
                float2 h = upk(an2[rp]); pp[32 + 2*rp] = h.x; pp[32 + 2*rp + 1] = h.y;
            }
        }
        __syncthreads();

        if (g == 0) {
            const float* pp = sh_part + tj * 49;
            float hnew[ROWS];
            #pragma unroll
            for (int rp = 0; rp < RP; ++rp) {
                float2 vr = upk(ar[rp]);  vr.x += pp[2*rp];      vr.y += pp[2*rp + 1];
                float2 vz = upk(az[rp]);  vz.x += pp[16 + 2*rp]; vz.y += pp[16 + 2*rp + 1];
                float2 vi = upk(an1[rp]);
                float2 vh = upk(an2[rp]); vh.x += pp[32 + 2*rp]; vh.y += pp[32 + 2*rp + 1];
                float r0 = sigmoidf_(vr.x), r1 = sigmoidf_(vr.y);
                float z0 = sigmoidf_(vz.x), z1 = sigmoidf_(vz.y);
                float n0 = tanhf_(vi.x + r0 * vh.x);
                float n1 = tanhf_(vi.y + r1 * vh.y);
                float o0 = sh_h[tj * PAD + 2 * rp];
                float o1 = sh_h[tj * PAD + 2 * rp + 1];
                hnew[2*rp]     = (1.f - z0) * n0 + z0 * o0;
                hnew[2*rp + 1] = (1.f - z1) * n1 + z1 * o1;
            }
            size_t base = ((size_t)row0 * TDIM + step) * HDIM + tj;
            #pragma unroll
            for (int r = 0; r < ROWS; ++r) {
                sh_h[tj * PAD + r] = hnew[r];
                g_hsh[base + (size_t)r * TDIM * HDIM] = __float2half_rn(hnew[r]);
            }
            // fused A/C partials (fp32, warp-reduced)
            float pa[ROWS], pc[ROWS];
            #pragma unroll
            for (int r = 0; r < ROWS; ++r) { pa[r] = hnew[r] * wqv; pc[r] = hnew[r] * bqv; }
            #pragma unroll
            for (int off = 16; off; off >>= 1) {
                #pragma unroll
                for (int r = 0; r < ROWS; ++r) {
                    pa[r] += __shfl_xor_sync(0xffffffffu, pa[r], off);
                    pc[r] += __shfl_xor_sync(0xffffffffu, pc[r], off);
                }
            }
            if ((tj & 31) == 0) {
                #pragma unroll
                for (int r = 0; r < ROWS; ++r) {
                    sh_ac[wp * 32 + r * 2]     = pa[r];
                    sh_ac[wp * 32 + r * 2 + 1] = pc[r];
                }
            }
        } else if (step + 1 < TDIM) {
            for (int i = tj; i < ROWS * FDIM; i += 256) {
                int r = i >> 6, f = i & 63;
                xn[f * PAD + r] = x[((size_t)(row0 + r) * TDIM + (step + 1)) * FDIM + f];
            }
        }
        __syncthreads();
        if (t < 32) {
            int r = t >> 1, isC = t & 1;
            float s = 0.f;
            #pragma unroll
            for (int w = 0; w < 8; ++w) s += sh_ac[w * 32 + r * 2 + isC];
            if (isC) g_C[(row0 + r) * TDIM + step] = s;
            else     g_A[(row0 + r) * TDIM + step] = s;
        }
    }
}

// ---------------- decoder: 512 threads, split-K, fp16 hs for ctx ----------------
// smem float offsets
#define D_CTX  0                     // 256*PAD = 4608
#define D_A    4608                  // 16*128  = 2048
#define D_C    6656
#define D_W    8704
#define D_PART 10752                 // 256*48 = 12288
#define D_PREV 23040                 // 16
#define D_RED  23056                 // 16*16 = 256
#define DEC_SMEM_FLOATS 23312        // 93248 bytes

__global__ void __launch_bounds__(512, 1)
decoder_kernel(const float* __restrict__ x,
               const float* __restrict__ dWih, const float* __restrict__ dbih,
               const float* __restrict__ dbhh,
               const float* __restrict__ fc1b, const float* __restrict__ fc2W,
               const float* __restrict__ fc2b, float* __restrict__ out) {
    extern __shared__ float dsm[];
    float* sh_ctx  = dsm + D_CTX;
    float* sh_A    = dsm + D_A;
    float* sh_C    = dsm + D_C;
    float* sh_w    = dsm + D_W;
    float* sh_part = dsm + D_PART;
    float* sh_prev = dsm + D_PREV;
    float* sh_red  = dsm + D_RED;

    const int t = threadIdx.x;
    const int row0 = blockIdx.x * ROWS;
    const int wp = t >> 5, lane = t & 31;
    const int g2 = t >> 8, tj = t & 255;
    const int qg = t >> 7, h2 = t & 127;

    for (int i = t; i < ROWS * TDIM; i += 512) {
        int r = i >> 7, tt = i & 127;
        sh_A[r * TDIM + tt] = g_A[(row0 + r) * TDIM + tt];
        sh_C[r * TDIM + tt] = g_C[(row0 + r) * TDIM + tt];
    }
    if (t < ROWS)
        sh_prev[t] = x[((size_t)(row0 + t) * TDIM + (TDIM - 1)) * FDIM + 0];

    const float dbr  = dbih[tj]          + dbhh[tj];
    const float dbz  = dbih[tj + HDIM]   + dbhh[tj + HDIM];
    const float dbin = dbih[tj + 2*HDIM];
    const float dbhn = dbhh[tj + 2*HDIM];
    const float wir  = dWih[tj], wiz = dWih[tj + HDIM], win = dWih[tj + 2*HDIM];
    const float f1b  = fc1b[tj];
    const float f2w  = fc2W[tj];
    const float f2b  = fc2b[0];
    const float scale = 0.0625f;   // 1/sqrt(256)
    __syncthreads();

    for (int step = 0; step < OUTL; ++step) {
        // ---- scores + softmax: one warp per row ----
        {
            int r = wp;
            float pv = sh_prev[r];
            float sv[4], m = -1e30f;
            #pragma unroll
            for (int i = 0; i < 4; ++i) {
                int tt = lane + 32 * i;
                float s = (pv * sh_A[r * TDIM + tt] + sh_C[r * TDIM + tt]) * scale;
                sv[i] = s; m = fmaxf(m, s);
            }
            #pragma unroll
            for (int off = 16; off; off >>= 1) m = fmaxf(m, __shfl_xor_sync(0xffffffffu, m, off));
            float sum = 0.f;
            #pragma unroll
            for (int i = 0; i < 4; ++i) { sv[i] = __expf(sv[i] - m); sum += sv[i]; }
            #pragma unroll
            for (int off = 16; off; off >>= 1) sum += __shfl_xor_sync(0xffffffffu, sum, off);
            float inv = __fdividef(1.f, sum);
            #pragma unroll
            for (int i = 0; i < 4; ++i) sh_w[r * TDIM + lane + 32 * i] = sv[i] * inv;
        }
        __syncthreads();

        // ---- ctx: thread covers 4 rows (qg) x 2 h (2*h2, 2*h2+1), fp16x2 loads ----
        {
            float a0x = 0.f, a0y = 0.f, a1x = 0.f, a1y = 0.f;
            float a2x = 0.f, a2y = 0.f, a3x = 0.f, a3y = 0.f;
            const __half* hb =
                g_hsh + ((size_t)(row0 + qg * 4) * TDIM) * HDIM + 2 * h2;
            const size_t rstride = (size_t)TDIM * HDIM;
            #pragma unroll 2
            for (int tt = 0; tt < TDIM; ++tt) {
                const __half* hp = hb + (size_t)tt * HDIM;
                __half2 v0 = *reinterpret_cast<const __half2*>(hp);
                __half2 v1 = *reinterpret_cast<const __half2*>(hp + rstride);
                __half2 v2 = *reinterpret_cast<const __half2*>(hp + 2 * rstride);
                __half2 v3 = *reinterpret_cast<const __half2*>(hp + 3 * rstride);
                float w0 = sh_w[(qg * 4 + 0) * TDIM + tt];
                float w1 = sh_w[(qg * 4 + 1) * TDIM + tt];
                float w2 = sh_w[(qg * 4 + 2) * TDIM + tt];
                float w3 = sh_w[(qg * 4 + 3) * TDIM + tt];
                float2 f0 = __half22float2(v0);
                float2 f1 = __half22float2(v1);
                float2 f2 = __half22float2(v2);
                float2 f3 = __half22float2(v3);
                a0x = fmaf(w0, f0.x, a0x); a0y = fmaf(w0, f0.y, a0y);
                a1x = fmaf(w1, f1.x, a1x); a1y = fmaf(w1, f1.y, a1y);
                a2x = fmaf(w2, f2.x, a2x); a2y = fmaf(w2, f2.y, a2y);
                a3x = fmaf(w3, f3.x, a3x); a3y = fmaf(w3, f3.y, a3y);
            }
            int hx = 2 * h2, r0 = qg * 4;
            sh_ctx[hx * PAD + r0 + 0] = a0x; sh_ctx[(hx + 1) * PAD + r0 + 0] = a0y;
            sh_ctx[hx * PAD + r0 + 1] = a1x; sh_ctx[(hx + 1) * PAD + r0 + 1] = a1y;
            sh_ctx[hx * PAD + r0 + 2] = a2x; sh_ctx[(hx + 1) * PAD + r0 + 2] = a2y;
            sh_ctx[hx * PAD + r0 + 3] = a3x; sh_ctx[(hx + 1) * PAD + r0 + 3] = a3y;
        }
        __syncthreads();

        // ---- GRU cell (split-K: g2=0 -> k 0..127, g2=1 -> k 128..255) ----
        u64 ar[RP], az[RP], ahn[RP], ain[RP];
        if (g2 == 0) {
            #pragma unroll
            for (int rp = 0; rp < RP; ++rp) {
                float p0 = sh_prev[2*rp], p1 = sh_prev[2*rp + 1];
                ar[rp]  = pk2p(fmaf(p0, wir, dbr),  fmaf(p1, wir, dbr));
                az[rp]  = pk2p(fmaf(p0, wiz, dbz),  fmaf(p1, wiz, dbz));
                ain[rp] = pk2p(fmaf(p0, win, dbin), fmaf(p1, win, dbin));
                ahn[rp] = pk2(dbhn);
            }
        } else {
            u64 z0 = pk2(0.f);
            #pragma unroll
            for (int rp = 0; rp < RP; ++rp) { ar[rp]=z0; az[rp]=z0; ahn[rp]=z0; ain[rp]=z0; }
        }
        {
            const int k0 = g2 * 128;
            #pragma unroll 2
            for (int kk = 0; kk < 128; ++kk) {
                int k = k0 + kk;
                float2 w  = g_DWrz[k * 256 + tj];
                float  wn = g_DWn [k * 256 + tj];
                u64 wr = pk2(w.x), wzv = pk2(w.y), wn2 = pk2(wn);
                #pragma unroll
                for (int rp = 0; rp < RP; ++rp) {
                    u64 cv = lds2(&sh_ctx[k * PAD + 2*rp]);
                    fma2(ar[rp],  cv, wr);
                    fma2(az[rp],  cv, wzv);
                    fma2(ahn[rp], cv, wn2);
                }
            }
        }
        if (g2 == 1) {
            float* pp = sh_part + tj * 48;
            #pragma unroll
            for (int rp = 0; rp < RP; ++rp) {
                float2 v = upk(ar[rp]);  pp[2*rp]      = v.x; pp[2*rp + 1]      = v.y;
                float2 w = upk(az[rp]);  pp[16 + 2*rp] = w.x; pp[16 + 2*rp + 1] = w.y;
                float2 h = upk(ahn[rp]); pp[32 + 2*rp] = h.x; pp[32 + 2*rp + 1] = h.y;
            }
        }
        __syncthreads();

        if (g2 == 0) {
            const float* pp = sh_part + tj * 48;
            float hd[ROWS];
            #pragma unroll
            for (int rp = 0; rp < RP; ++rp) {
                float2 vr = upk(ar[rp]);  vr.x += pp[2*rp];      vr.y += pp[2*rp + 1];
                float2 vz = upk(az[rp]);  vz.x += pp[16 + 2*rp]; vz.y += pp[16 + 2*rp + 1];
                float2 vi = upk(ain[rp]);
                float2 vh = upk(ahn[rp]); vh.x += pp[32 + 2*rp]; vh.y += pp[32 + 2*rp + 1];
                float r0 = sigmoidf_(vr.x), r1 = sigmoidf_(vr.y);
                float z0 = sigmoidf_(vz.x), z1 = sigmoidf_(vz.y);
                float n0 = tanhf_(vi.x + r0 * vh.x);
                float n1 = tanhf_(vi.y + r1 * vh.y);
                float c0 = sh_ctx[tj * PAD + 2*rp];
                float c1 = sh_ctx[tj * PAD + 2*rp + 1];
                hd[2*rp]     = (1.f - z0) * n0 + z0 * c0;
                hd[2*rp + 1] = (1.f - z1) * n1 + z1 * c1;
            }
            #pragma unroll
            for (int r = 0; r < ROWS; ++r) sh_ctx[tj * PAD + r] = hd[r];
        }
        __syncthreads();

        // ---- fc1 (relu), split-K ----
        u64 a1[RP];
        {
            u64 b1 = (g2 == 0) ? pk2(f1b) : pk2(0.f);
            #pragma unroll
            for (int rp = 0; rp < RP; ++rp) a1[rp] = b1;
            const int k0 = g2 * 128;
            #pragma unroll 2
            for (int kk = 0; kk < 128; ++kk) {
                int k = k0 + kk;
                u64 wf = pk2(g_WtFc1[k * FCH + tj]);
                #pragma unroll
                for (int rp = 0; rp < RP; ++rp) {
                    u64 hv = lds2(&sh_ctx[k * PAD + 2*rp]);
                    fma2(a1[rp], hv, wf);
                }
            }
        }
        if (g2 == 1) {
            float* pp = sh_part + tj * 48;
            #pragma unroll
            for (int rp = 0; rp < RP; ++rp) {
                float2 v = upk(a1[rp]);
                pp[2*rp] = v.x; pp[2*rp + 1] = v.y;
            }
        }
        __syncthreads();

        if (g2 == 0) {
            const float* pp = sh_part + tj * 48;
            float p[ROWS];
            #pragma unroll
            for (int rp = 0; rp < RP; ++rp) {
                float2 v = upk(a1[rp]);
                p[2*rp]     = fmaxf(v.x + pp[2*rp],     0.f) * f2w;
                p[2*rp + 1] = fmaxf(v.y + pp[2*rp + 1], 0.f) * f2w;
            }
            #pragma unroll
            for (int off = 16; off; off >>= 1) {
                #pragma unroll
                for (int r = 0; r < ROWS; ++r)
                    p[r] += __shfl_xor_sync(0xffffffffu, p[r], off);
            }
            if (lane == 0) {
                #pragma unroll
                for (int r = 0; r < ROWS; ++r) sh_red[wp * ROWS + r] = p[r];
            }
        }
        __syncthreads();
        if (t < ROWS) {
            float s = f2b;
            #pragma unroll
            for (int w = 0; w < 8; ++w) s += sh_red[w * ROWS + t];
            out[(size_t)(row0 + t) * OUTL + step] = s;
            sh_prev[t] = s;
        }
        __syncthreads();
    }
}

// ---------------- launch ----------------
extern "C" void kernel_launch(void* const* d_in, const int* in_sizes, int n_in,
                              void* d_out, int out_size) {
    (void)in_sizes; (void)n_in; (void)out_size;
    const float* x       = (const float*)d_in[0];
    const float* h0      = (const float*)d_in[1];
    const float* enc_Wih = (const float*)d_in[2];
    const float* enc_Whh = (const float*)d_in[3];
    const float* enc_bih = (const float*)d_in[4];
    const float* enc_bhh = (const float*)d_in[5];
    const float* dec_Wih = (const float*)d_in[6];
    const float* dec_Whh = (const float*)d_in[7];
    const float* dec_bih = (const float*)d_in[8];
    const float* dec_bhh = (const float*)d_in[9];
    const float* attn_Wq = (const float*)d_in[10];
    const float* attn_bq = (const float*)d_in[11];
    const float* fc1_W   = (const float*)d_in[12];
    const float* fc1_b   = (const float*)d_in[13];
    const float* fc2_W   = (const float*)d_in[14];
    const float* fc2_b   = (const float*)d_in[15];
    float* out = (float*)d_out;

    const int enc_smem = ENC_SMEM_FLOATS * (int)sizeof(float);   // 78848 B
    const int dec_smem = DEC_SMEM_FLOATS * (int)sizeof(float);   // 93248 B
    cudaFuncSetAttribute(encoder_kernel,
                         cudaFuncAttributeMaxDynamicSharedMemorySize, enc_smem);
    cudaFuncSetAttribute(decoder_kernel,
                         cudaFuncAttributeMaxDynamicSharedMemorySize, dec_smem);

    prep_kernel<<<(320 * 256 + NTHR - 1) / NTHR, NTHR>>>(enc_Wih, enc_Whh, dec_Whh, fc1_W);
    encoder_kernel<<<NCTA, 512, enc_smem>>>(x, h0, enc_bih, enc_bhh, attn_Wq, attn_bq);
    decoder_kernel<<<NCTA, 512, dec_smem>>>(x, dec_Wih, dec_bih, dec_bhh,
                                            fc1_b, fc2_W, fc2_b, out);
}